// round 11
// baseline (speedup 1.0000x reference)
#include <cuda_runtime.h>
#include <cuda_bf16.h>
#include <cuda_fp16.h>
#include <cstdint>

// Problem-fixed maxima (sizes also derived at runtime from in_sizes)
#define NMAX 100000
#define EMAX 1600000
#define HID  128
#define INF  256

#define SCHUNK 1024
#define SBLOCKS_MAX 128   // ceil(NMAX/SCHUNK)=98 <= 128

// ---------------- scratch (device globals: no allocation allowed) ----------
__device__ __align__(256) __half g_bufH[(size_t)NMAX * HID];          // gathered GEMM out
__device__ __align__(256) __nv_bfloat16 g_aHi[(size_t)NMAX * HID];    // A hi plane (layers)
__device__ __align__(256) __nv_bfloat16 g_aLo[(size_t)NMAX * HID];    // A lo plane
__device__ __align__(256) __nv_bfloat16 g_xHi[(size_t)NMAX * INF];    // x hi plane (embed)
__device__ __align__(256) __nv_bfloat16 g_xLo[(size_t)NMAX * INF];    // x lo plane
__device__ __align__(16)  int   g_eidx0[EMAX];
__device__ __align__(16)  int   g_eidx1[EMAX];
__device__ __align__(16)  int   g_rs0[NMAX + 1];
__device__ __align__(16)  int   g_rs1[NMAX + 1];
__device__ int g_do0[NMAX], g_di0[NMAX], g_do1[NMAX], g_di1[NMAX];
__device__ int g_cur0[NMAX], g_cur1[NMAX];
__device__ float g_ns0[NMAX], g_nd0[NMAX], g_ns1[NMAX], g_nd1[NMAX];
__device__ int g_part[2][SBLOCKS_MAX];
__device__ int g_pscan[2][SBLOCKS_MAX];
// W transposed + bf16 hi/lo split scratch: [HID rows][K<=256], K-contiguous
__device__ __align__(16) __nv_bfloat16 g_wHi[HID * 256];
__device__ __align__(16) __nv_bfloat16 g_wLo[HID * 256];

// ---------------- helpers ---------------------------------------------------
__device__ __forceinline__ uint32_t smem_u32(const void* p) {
    uint32_t a;
    asm("{ .reg .u64 t; cvta.to.shared.u64 t, %1; cvt.u32.u64 %0, t; }"
        : "=r"(a) : "l"(p));
    return a;
}

__device__ __forceinline__ uint32_t b2u(__nv_bfloat162 h) {
    return *reinterpret_cast<uint32_t*>(&h);
}

// split 2 floats into packed hi bf16x2 and lo bf16x2 (compensated)
__device__ __forceinline__ void split2(float a, float b, uint32_t& hi, uint32_t& lo) {
    __nv_bfloat162 h = __float22bfloat162_rn(make_float2(a, b));
    float la = a - __low2float(h);
    float lb = b - __high2float(h);
    __nv_bfloat162 l = __float22bfloat162_rn(make_float2(la, lb));
    hi = b2u(h);
    lo = b2u(l);
}

#define LDSM4(r, addr) \
    asm volatile("ldmatrix.sync.aligned.m8n8.x4.shared.b16 {%0,%1,%2,%3}, [%4];" \
                 : "=r"((r)[0]), "=r"((r)[1]), "=r"((r)[2]), "=r"((r)[3]) \
                 : "r"(addr))

#define MMA16816(d, a, b0, b1) \
    asm volatile("mma.sync.aligned.m16n8k16.row.col.f32.bf16.bf16.f32 " \
                 "{%0,%1,%2,%3}, {%4,%5,%6,%7}, {%8,%9}, {%0,%1,%2,%3};" \
                 : "+f"((d)[0]), "+f"((d)[1]), "+f"((d)[2]), "+f"((d)[3]) \
                 : "r"((a)[0]), "r"((a)[1]), "r"((a)[2]), "r"((a)[3]), \
                   "r"(b0), "r"(b1))

// 16B async copy global->shared; src_size=0 zero-fills (OOB guard)
__device__ __forceinline__ void cpa16(uint32_t dst, const void* src, bool full) {
    asm volatile("cp.async.cg.shared.global [%0], [%1], 16, %2;"
                 :: "r"(dst), "l"(src), "r"(full ? 16u : 0u) : "memory");
}
#define CPA_COMMIT() asm volatile("cp.async.commit_group;" ::: "memory")
#define CPA_WAIT1()  asm volatile("cp.async.wait_group 1;" ::: "memory")

// ---------------- setup kernels --------------------------------------------
__global__ void count_deg(const int* __restrict__ s0, const int* __restrict__ d0,
                          const int* __restrict__ s1, const int* __restrict__ d1, int e) {
    int i = blockIdx.x * blockDim.x + threadIdx.x;
    if (i < e) {
        atomicAdd(&g_do0[s0[i]], 1);
        atomicAdd(&g_di0[d0[i]], 1);
        atomicAdd(&g_do1[s1[i]], 1);
        atomicAdd(&g_di1[d1[i]], 1);
    }
}

__global__ void norms_k(int n) {
    int i = blockIdx.x * blockDim.x + threadIdx.x;
    if (i < n) {
        g_ns0[i] = rsqrtf(fmaxf((float)g_do0[i], 1.0f));
        g_nd0[i] = rsqrtf(fmaxf((float)g_di0[i], 1.0f));
        g_ns1[i] = rsqrtf(fmaxf((float)g_do1[i], 1.0f));
        g_nd1[i] = rsqrtf(fmaxf((float)g_di1[i], 1.0f));
    }
}

// W prep: transpose + bf16 hi/lo split.  W:[K][HID] -> wt{Hi,Lo}:[HID][K]
__global__ void w_prep(const float* __restrict__ W, int K) {
    int idx = blockIdx.x * blockDim.x + threadIdx.x;
    if (idx < K * HID) {
        int k = idx / HID, n = idx % HID;
        float w = W[idx];
        __nv_bfloat16 h = __float2bfloat16(w);
        float l = w - __bfloat162float(h);
        g_wHi[n * K + k] = h;
        g_wLo[n * K + k] = __float2bfloat16(l);
    }
}

// x prep: split fp32 x into bf16 hi/lo planes (same layout)
__global__ void x_prep(const float* __restrict__ x,
                       __nv_bfloat16* __restrict__ xHi,
                       __nv_bfloat16* __restrict__ xLo, int total4) {
    int i = blockIdx.x * blockDim.x + threadIdx.x;
    if (i < total4) {
        float4 v = *reinterpret_cast<const float4*>(x + (size_t)i * 4);
        uint32_t h0, l0, h1, l1;
        split2(v.x, v.y, h0, l0);
        split2(v.z, v.w, h1, l1);
        *reinterpret_cast<uint2*>(xHi + (size_t)i * 4) = make_uint2(h0, h1);
        *reinterpret_cast<uint2*>(xLo + (size_t)i * 4) = make_uint2(l0, l1);
    }
}

// ---------------- grid-wide exclusive scan (3 passes, 2 arrays batched) ----
__global__ void scan_pass1(const int* __restrict__ dA, const int* __restrict__ dB, int n) {
    const int* deg = blockIdx.y ? dB : dA;
    __shared__ int sh[256];
    int base = blockIdx.x * SCHUNK + threadIdx.x * 4;
    int s = 0;
#pragma unroll
    for (int q = 0; q < 4; ++q)
        if (base + q < n) s += deg[base + q];
    sh[threadIdx.x] = s;
    __syncthreads();
#pragma unroll
    for (int off = 128; off > 0; off >>= 1) {
        if (threadIdx.x < off) sh[threadIdx.x] += sh[threadIdx.x + off];
        __syncthreads();
    }
    if (threadIdx.x == 0) g_part[blockIdx.y][blockIdx.x] = sh[0];
}

__global__ void scan_pass2(int* __restrict__ rsA, int* __restrict__ rsB,
                           int nblocks, int n) {
    __shared__ int sh[2][SBLOCKS_MAX];
    int a = threadIdx.x >> 7;
    int j = threadIdx.x & 127;
    int v = (j < nblocks) ? g_part[a][j] : 0;
    sh[a][j] = v;
    __syncthreads();
#pragma unroll
    for (int off = 1; off < SBLOCKS_MAX; off <<= 1) {
        int t = (j >= off) ? sh[a][j - off] : 0;
        __syncthreads();
        sh[a][j] += t;
        __syncthreads();
    }
    if (j < nblocks) g_pscan[a][j] = sh[a][j] - v;   // exclusive
    if (j == 127) {
        int total = sh[a][SBLOCKS_MAX - 1];
        (a ? rsB : rsA)[n] = total;
    }
}

__global__ void scan_pass3(const int* __restrict__ dA, const int* __restrict__ dB,
                           int* __restrict__ rsA, int* __restrict__ rsB, int n) {
    const int* deg = blockIdx.y ? dB : dA;
    int* rs = blockIdx.y ? rsB : rsA;
    __shared__ int sh[256];
    int base = blockIdx.x * SCHUNK + threadIdx.x * 4;
    int v[4];
    int s = 0;
#pragma unroll
    for (int q = 0; q < 4; ++q) {
        v[q] = (base + q < n) ? deg[base + q] : 0;
        s += v[q];
    }
    sh[threadIdx.x] = s;
    __syncthreads();
#pragma unroll
    for (int off = 1; off < 256; off <<= 1) {
        int t = (threadIdx.x >= off) ? sh[threadIdx.x - off] : 0;
        __syncthreads();
        sh[threadIdx.x] += t;
        __syncthreads();
    }
    int ex = sh[threadIdx.x] - s + g_pscan[blockIdx.y][blockIdx.x];
#pragma unroll
    for (int q = 0; q < 4; ++q) {
        if (base + q < n) { rs[base + q] = ex; ex += v[q]; }
    }
}

__global__ void fill_csr(const int* __restrict__ src, const int* __restrict__ dst,
                         const int* __restrict__ rs, int* __restrict__ cur,
                         int* __restrict__ eidx, int e) {
    int i = blockIdx.x * blockDim.x + threadIdx.x;
    if (i < e) {
        int d = dst[i];
        int p = atomicAdd(&cur[d], 1);
        eidx[rs[d] + p] = src[i];
    }
}

// ============== pipelined mma.sync bf16x3 GEMM ==============================
// Block: 256 threads = 8 warps (4 m x 2 n), tile 128x128, K-chunk 64,
// cp.async double-buffered SMEM. Rows padded to 144 B -> conflict-free ldmatrix.
#define ROWB 144
#define OFF_AHI 0
#define OFF_ALO (128 * ROWB)
#define OFF_WHI (2 * 128 * ROWB)
#define OFF_WLO (3 * 128 * ROWB)
#define BUFB    (4 * 128 * ROWB)      // 73728 B per buffer
#define GSMEMP  (2 * BUFB)            // 147456 B

struct WarpCtx {
    uint32_t aHiOff, aLoOff, wHiOff, wLoOff;
    int warp_m, warp_n, lane;
};

__device__ __forceinline__ WarpCtx mk_ctx(int tid) {
    WarpCtx c;
    int wid = tid >> 5;
    c.lane = tid & 31;
    c.warp_m = wid & 3;
    c.warp_n = wid >> 2;
    const int q4 = c.lane >> 3, lr = c.lane & 7;
    const uint32_t laneA = (uint32_t)(((q4 & 1) * 8 + lr) * ROWB + (q4 >> 1) * 16);
    const uint32_t laneB = (uint32_t)(((q4 >> 1) * 8 + lr) * ROWB + (q4 & 1) * 16);
    c.aHiOff = OFF_AHI + (uint32_t)(c.warp_m * 32) * ROWB + laneA;
    c.aLoOff = OFF_ALO + (uint32_t)(c.warp_m * 32) * ROWB + laneA;
    c.wHiOff = OFF_WHI + (uint32_t)(c.warp_n * 64) * ROWB + laneB;
    c.wLoOff = OFF_WLO + (uint32_t)(c.warp_n * 64) * ROWB + laneB;
    return c;
}

// stage one K=64 chunk of A planes + W planes into buffer at base (cp.async)
template <int K>
__device__ __forceinline__ void stage_chunk(uint32_t base,
                                            const __nv_bfloat16* __restrict__ aHi,
                                            const __nv_bfloat16* __restrict__ aLo,
                                            const __nv_bfloat16* __restrict__ whi,
                                            const __nv_bfloat16* __restrict__ wlo,
                                            int kc, int block_m, int M, int tid) {
#pragma unroll
    for (int i = 0; i < 4; ++i) {
        int idx = tid + i * 256;          // 0..1023
        int r = idx >> 3;                 // 0..127
        int c8 = (idx & 7) * 8;           // bf16 col, 16B granules
        uint32_t off = (uint32_t)(r * ROWB + c8 * 2);
        // A row (guard OOB rows: clamp address, zero-fill via src_size=0)
        int gm = block_m + r;
        bool ok = gm < M;
        size_t goA = ok ? ((size_t)gm * K + kc + c8) : 0;
        cpa16(base + OFF_AHI + off, aHi + goA, ok);
        cpa16(base + OFF_ALO + off, aLo + goA, ok);
        // W row (always full 128 rows)
        size_t goW = (size_t)r * K + kc + c8;
        cpa16(base + OFF_WHI + off, whi + goW, true);
        cpa16(base + OFF_WLO + off, wlo + goW, true);
    }
}

__device__ __forceinline__ void compute_chunk(uint32_t base, const WarpCtx& c,
                                              float acc[2][8][4]) {
#pragma unroll
    for (int ks = 0; ks < 4; ++ks) {
        uint32_t ahi[2][4], alo[2][4];
#pragma unroll
        for (int ma = 0; ma < 2; ++ma) {
            uint32_t ao = (uint32_t)(ma * 16 * ROWB + ks * 32);
            LDSM4(ahi[ma], base + c.aHiOff + ao);
            LDSM4(alo[ma], base + c.aLoOff + ao);
        }
#pragma unroll
        for (int nb = 0; nb < 4; ++nb) {
            uint32_t bhi[4], blo[4];
            uint32_t bo = (uint32_t)(nb * 16 * ROWB + ks * 32);
            LDSM4(bhi, base + c.wHiOff + bo);
            LDSM4(blo, base + c.wLoOff + bo);
#pragma unroll
            for (int ma = 0; ma < 2; ++ma) {
                MMA16816(acc[ma][nb * 2 + 0], ahi[ma], bhi[0], bhi[1]);
                MMA16816(acc[ma][nb * 2 + 0], ahi[ma], blo[0], blo[1]);
                MMA16816(acc[ma][nb * 2 + 0], alo[ma], bhi[0], bhi[1]);
                MMA16816(acc[ma][nb * 2 + 1], ahi[ma], bhi[2], bhi[3]);
                MMA16816(acc[ma][nb * 2 + 1], ahi[ma], blo[2], blo[3]);
                MMA16816(acc[ma][nb * 2 + 1], alo[ma], bhi[2], bhi[3]);
            }
        }
    }
}

// MODE 0: out = planes(acc + bias)   (embed)
// MODE 1: out = fp16(acc * rowscale) (layers)
template <int K, int MODE>
__global__ __launch_bounds__(256, 1)
void gemm_pipe(const __nv_bfloat16* __restrict__ aHi,
               const __nv_bfloat16* __restrict__ aLo,
               const __nv_bfloat16* __restrict__ whi,
               const __nv_bfloat16* __restrict__ wlo,
               const float* __restrict__ bias, const float* __restrict__ rowscale,
               __nv_bfloat16* __restrict__ outHi, __nv_bfloat16* __restrict__ outLo,
               __half* __restrict__ outH, int M) {
    extern __shared__ char sm[];
    const uint32_t smb = smem_u32(sm);
    const int tid = threadIdx.x;
    const int block_m = blockIdx.x * 128;
    WarpCtx c = mk_ctx(tid);

    float acc[2][8][4];
#pragma unroll
    for (int i = 0; i < 2; ++i)
#pragma unroll
        for (int j = 0; j < 8; ++j)
#pragma unroll
            for (int q = 0; q < 4; ++q) acc[i][j][q] = 0.0f;

    constexpr int NC = K / 64;
    // prologue: stage chunk 0
    stage_chunk<K>(smb, aHi, aLo, whi, wlo, 0, block_m, M, tid);
    CPA_COMMIT();
#pragma unroll
    for (int ch = 0; ch < NC; ++ch) {
        if (ch + 1 < NC)
            stage_chunk<K>(smb + ((ch + 1) & 1) * BUFB, aHi, aLo, whi, wlo,
                           (ch + 1) * 64, block_m, M, tid);
        CPA_COMMIT();          // uniform: one group per iteration
        CPA_WAIT1();           // chunk ch's group complete
        __syncthreads();
        compute_chunk(smb + (ch & 1) * BUFB, c, acc);
        __syncthreads();       // all reads of this buffer done before re-stage
    }

    // ---- epilogue ----
    const int g = c.lane >> 2, t = c.lane & 3;
#pragma unroll
    for (int ma = 0; ma < 2; ++ma) {
        int r0 = block_m + c.warp_m * 32 + ma * 16 + g;
        int r1 = r0 + 8;
        float rs0 = 1.f, rs1 = 1.f;
        if (MODE == 1) {
            rs0 = (r0 < M) ? rowscale[r0] : 0.f;
            rs1 = (r1 < M) ? rowscale[r1] : 0.f;
        }
#pragma unroll
        for (int na = 0; na < 8; ++na) {
            int col = c.warp_n * 64 + na * 8 + t * 2;
            if (MODE == 0) {
                float2 bv = *reinterpret_cast<const float2*>(bias + col);
                if (r0 < M) {
                    uint32_t h, l;
                    split2(acc[ma][na][0] + bv.x, acc[ma][na][1] + bv.y, h, l);
                    *reinterpret_cast<uint32_t*>(outHi + (size_t)r0 * HID + col) = h;
                    *reinterpret_cast<uint32_t*>(outLo + (size_t)r0 * HID + col) = l;
                }
                if (r1 < M) {
                    uint32_t h, l;
                    split2(acc[ma][na][2] + bv.x, acc[ma][na][3] + bv.y, h, l);
                    *reinterpret_cast<uint32_t*>(outHi + (size_t)r1 * HID + col) = h;
                    *reinterpret_cast<uint32_t*>(outLo + (size_t)r1 * HID + col) = l;
                }
            } else {
                if (r0 < M) {
                    __half2 o = __floats2half2_rn(acc[ma][na][0] * rs0, acc[ma][na][1] * rs0);
                    *reinterpret_cast<__half2*>(outH + (size_t)r0 * HID + col) = o;
                }
                if (r1 < M) {
                    __half2 o = __floats2half2_rn(acc[ma][na][2] * rs1, acc[ma][na][3] * rs1);
                    *reinterpret_cast<__half2*>(outH + (size_t)r1 * HID + col) = o;
                }
            }
        }
    }
}

// ---------------- CSR aggregation + fused epilogues ------------------------
__device__ __forceinline__ float4 agg_core(const int* __restrict__ eidx,
                                           const __half* __restrict__ B,
                                           int beg, int end, int lane) {
    float4 a0 = make_float4(0.f, 0.f, 0.f, 0.f);
    float4 a1 = make_float4(0.f, 0.f, 0.f, 0.f);
    const int co = lane * 4;
    int i = beg;
    for (; i + 3 < end; i += 4) {
        int s0 = eidx[i], s1 = eidx[i + 1], s2 = eidx[i + 2], s3 = eidx[i + 3];
        uint2 u0 = *reinterpret_cast<const uint2*>(B + (size_t)s0 * HID + co);
        uint2 u1 = *reinterpret_cast<const uint2*>(B + (size_t)s1 * HID + co);
        uint2 u2 = *reinterpret_cast<const uint2*>(B + (size_t)s2 * HID + co);
        uint2 u3 = *reinterpret_cast<const uint2*>(B + (size_t)s3 * HID + co);
        float2 f;
        f = __half22float2(*reinterpret_cast<__half2*>(&u0.x)); a0.x += f.x; a0.y += f.y;
        f = __half22float2(*reinterpret_cast<__half2*>(&u0.y)); a0.z += f.x; a0.w += f.y;
        f = __half22float2(*reinterpret_cast<__half2*>(&u1.x)); a1.x += f.x; a1.y += f.y;
        f = __half22float2(*reinterpret_cast<__half2*>(&u1.y)); a1.z += f.x; a1.w += f.y;
        f = __half22float2(*reinterpret_cast<__half2*>(&u2.x)); a0.x += f.x; a0.y += f.y;
        f = __half22float2(*reinterpret_cast<__half2*>(&u2.y)); a0.z += f.x; a0.w += f.y;
        f = __half22float2(*reinterpret_cast<__half2*>(&u3.x)); a1.x += f.x; a1.y += f.y;
        f = __half22float2(*reinterpret_cast<__half2*>(&u3.y)); a1.z += f.x; a1.w += f.y;
    }
    for (; i < end; ++i) {
        int s0 = eidx[i];
        uint2 u0 = *reinterpret_cast<const uint2*>(B + (size_t)s0 * HID + co);
        float2 f;
        f = __half22float2(*reinterpret_cast<__half2*>(&u0.x)); a0.x += f.x; a0.y += f.y;
        f = __half22float2(*reinterpret_cast<__half2*>(&u0.y)); a0.z += f.x; a0.w += f.y;
    }
    a0.x += a1.x; a0.y += a1.y; a0.z += a1.z; a0.w += a1.w;
    return a0;
}

__global__ void agg_relu_planes(const int* __restrict__ eidx, const int* __restrict__ rs,
                                const __half* __restrict__ B, const float* __restrict__ nd,
                                const float* __restrict__ bias,
                                __nv_bfloat16* __restrict__ outHi,
                                __nv_bfloat16* __restrict__ outLo, int n) {
    int t = blockIdx.x * blockDim.x + threadIdx.x;
    int v = t >> 5;
    int lane = t & 31;
    if (v >= n) return;
    float4 acc = agg_core(eidx, B, rs[v], rs[v + 1], lane);
    float d = nd[v];
    float4 bv = *reinterpret_cast<const float4*>(bias + lane * 4);
    float o0 = fmaxf(fmaf(acc.x, d, bv.x), 0.f);
    float o1 = fmaxf(fmaf(acc.y, d, bv.y), 0.f);
    float o2 = fmaxf(fmaf(acc.z, d, bv.z), 0.f);
    float o3 = fmaxf(fmaf(acc.w, d, bv.w), 0.f);
    uint32_t h0, l0, h1, l1;
    split2(o0, o1, h0, l0);
    split2(o2, o3, h1, l1);
    size_t base = (size_t)v * HID + lane * 4;
    *reinterpret_cast<uint2*>(outHi + base) = make_uint2(h0, h1);
    *reinterpret_cast<uint2*>(outLo + base) = make_uint2(l0, l1);
}

__global__ void agg_relu_out(const int* __restrict__ eidx, const int* __restrict__ rs,
                             const __half* __restrict__ B, const float* __restrict__ nd,
                             const float* __restrict__ bias, float* __restrict__ out, int n) {
    int t = blockIdx.x * blockDim.x + threadIdx.x;
    int v = t >> 5;
    int lane = t & 31;
    if (v >= n) return;
    float4 acc = agg_core(eidx, B, rs[v], rs[v + 1], lane);
    float d = nd[v];
    float4 bv = *reinterpret_cast<const float4*>(bias + lane * 4);
    float4 o;
    o.x = fmaxf(fmaf(acc.x, d, bv.x), 0.f);
    o.y = fmaxf(fmaf(acc.y, d, bv.y), 0.f);
    o.z = fmaxf(fmaf(acc.z, d, bv.z), 0.f);
    o.w = fmaxf(fmaf(acc.w, d, bv.w), 0.f);
    *reinterpret_cast<float4*>(out + (size_t)v * HID + lane * 4) = o;
}

// ---------------- launch ----------------------------------------------------
extern "C" void kernel_launch(void* const* d_in, const int* in_sizes, int n_in,
                              void* d_out, int out_size) {
    const float* x  = (const float*)d_in[0];
    const float* We = (const float*)d_in[1];
    const float* be = (const float*)d_in[2];
    const float* W1 = (const float*)d_in[3];
    const float* b1 = (const float*)d_in[4];
    const float* W2 = (const float*)d_in[5];
    const float* b2 = (const float*)d_in[6];
    const int* src0 = (const int*)d_in[7];
    const int* dst0 = (const int*)d_in[8];
    const int* src1 = (const int*)d_in[9];
    const int* dst1 = (const int*)d_in[10];

    int n = in_sizes[0] / INF;
    int e = in_sizes[7];

    static bool attr_done = false;
    if (!attr_done) {
        cudaFuncSetAttribute(gemm_pipe<256, 0>, cudaFuncAttributeMaxDynamicSharedMemorySize, GSMEMP);
        cudaFuncSetAttribute(gemm_pipe<128, 1>, cudaFuncAttributeMaxDynamicSharedMemorySize, GSMEMP);
        attr_done = true;
    }

    float *pns0, *pnd0, *pns1, *pnd1;
    int *prs0, *prs1, *pe0, *pe1, *pc0, *pc1;
    int *pdo0, *pdi0, *pdo1, *pdi1;
    __nv_bfloat16 *pwHi, *pwLo, *paHi, *paLo, *pxHi, *pxLo;
    __half *pH;
    cudaGetSymbolAddress((void**)&pH,   g_bufH);
    cudaGetSymbolAddress((void**)&paHi, g_aHi);
    cudaGetSymbolAddress((void**)&paLo, g_aLo);
    cudaGetSymbolAddress((void**)&pxHi, g_xHi);
    cudaGetSymbolAddress((void**)&pxLo, g_xLo);
    cudaGetSymbolAddress((void**)&pns0, g_ns0);
    cudaGetSymbolAddress((void**)&pnd0, g_nd0);
    cudaGetSymbolAddress((void**)&pns1, g_ns1);
    cudaGetSymbolAddress((void**)&pnd1, g_nd1);
    cudaGetSymbolAddress((void**)&prs0, g_rs0);
    cudaGetSymbolAddress((void**)&prs1, g_rs1);
    cudaGetSymbolAddress((void**)&pe0,  g_eidx0);
    cudaGetSymbolAddress((void**)&pe1,  g_eidx1);
    cudaGetSymbolAddress((void**)&pc0,  g_cur0);
    cudaGetSymbolAddress((void**)&pc1,  g_cur1);
    cudaGetSymbolAddress((void**)&pdo0, g_do0);
    cudaGetSymbolAddress((void**)&pdi0, g_di0);
    cudaGetSymbolAddress((void**)&pdo1, g_do1);
    cudaGetSymbolAddress((void**)&pdi1, g_di1);
    cudaGetSymbolAddress((void**)&pwHi, g_wHi);
    cudaGetSymbolAddress((void**)&pwLo, g_wLo);

    int nb = (n + 255) / 256;
    int eb = (e + 255) / 256;
    int gb = (n + 127) / 128;
    long agg_threads = (long)n * 32;
    int ab = (int)((agg_threads + 255) / 256);
    int snb = (n + SCHUNK - 1) / SCHUNK;
    int x4 = n * INF / 4;

    // --- zero degree/cursor arrays via memset nodes (graph-capturable) ---
    cudaMemsetAsync(pdo0, 0, (size_t)n * sizeof(int));
    cudaMemsetAsync(pdi0, 0, (size_t)n * sizeof(int));
    cudaMemsetAsync(pdo1, 0, (size_t)n * sizeof(int));
    cudaMemsetAsync(pdi1, 0, (size_t)n * sizeof(int));
    cudaMemsetAsync(pc0,  0, (size_t)n * sizeof(int));
    cudaMemsetAsync(pc1,  0, (size_t)n * sizeof(int));

    // --- graph prep: degrees, norms, CSR-by-dst for both layers ---
    count_deg<<<eb, 256>>>(src0, dst0, src1, dst1, e);
    norms_k<<<nb, 256>>>(n);
    {
        dim3 sg(snb, 2);
        scan_pass1<<<sg, 256>>>(pdi0, pdi1, n);
        scan_pass2<<<1, 256>>>(prs0, prs1, snb, n);
        scan_pass3<<<sg, 256>>>(pdi0, pdi1, prs0, prs1, n);
    }
    fill_csr<<<eb, 256>>>(src0, dst0, prs0, pc0, pe0, e);
    fill_csr<<<eb, 256>>>(src1, dst1, prs1, pc1, pe1, e);

    // --- embed: planes(A) = x @ We + be ---
    x_prep<<<(x4 + 255) / 256, 256>>>(x, pxHi, pxLo, x4);
    w_prep<<<(256 * HID + 255) / 256, 256>>>(We, 256);
    gemm_pipe<256, 0><<<gb, 256, GSMEMP>>>(pxHi, pxLo, pwHi, pwLo, be, nullptr,
                                           paHi, paLo, nullptr, n);

    // --- layer 1: bufH = fp16((planes @ W1) * ns0) ; planes = relu(agg*nd0 + b1) ---
    w_prep<<<(128 * HID + 255) / 256, 256>>>(W1, 128);
    gemm_pipe<128, 1><<<gb, 256, GSMEMP>>>(paHi, paLo, pwHi, pwLo, nullptr, pns0,
                                           nullptr, nullptr, pH, n);
    agg_relu_planes<<<ab, 256>>>(pe0, prs0, pH, pnd0, b1, paHi, paLo, n);

    // --- layer 2: bufH = fp16((planes @ W2) * ns1) ; out = relu(agg*nd1 + b2) ---
    w_prep<<<(128 * HID + 255) / 256, 256>>>(W2, 128);
    gemm_pipe<128, 1><<<gb, 256, GSMEMP>>>(paHi, paLo, pwHi, pwLo, nullptr, pns1,
                                           nullptr, nullptr, pH, n);
    agg_relu_out<<<ab, 256>>>(pe1, prs1, pH, pnd1, b2, (float*)d_out, n);
}

// round 12
// speedup vs baseline: 1.0400x; 1.0400x over previous
#include <cuda_runtime.h>
#include <cuda_bf16.h>
#include <cuda_fp16.h>
#include <cstdint>

// Problem-fixed maxima (sizes also derived at runtime from in_sizes)
#define NMAX 100000
#define EMAX 1600000
#define HID  128
#define INF  256

#define SCHUNK 1024
#define SBLOCKS_MAX 128   // ceil(NMAX/SCHUNK)=98 <= 128

// ---------------- scratch (device globals: no allocation allowed) ----------
__device__ __align__(256) __half g_bufH[(size_t)NMAX * HID];          // gathered GEMM out
__device__ __align__(256) __nv_bfloat16 g_aHi[(size_t)NMAX * HID];    // A hi plane (layers)
__device__ __align__(256) __nv_bfloat16 g_aLo[(size_t)NMAX * HID];    // A lo plane
__device__ __align__(256) __nv_bfloat16 g_xHi[(size_t)NMAX * INF];    // x hi plane (embed)
__device__ __align__(256) __nv_bfloat16 g_xLo[(size_t)NMAX * INF];    // x lo plane
__device__ __align__(16)  int   g_eidx0[EMAX];
__device__ __align__(16)  int   g_eidx1[EMAX];
__device__ __align__(16)  int   g_rs0[NMAX + 1];
__device__ __align__(16)  int   g_rs1[NMAX + 1];
__device__ int g_do0[NMAX], g_di0[NMAX], g_do1[NMAX], g_di1[NMAX];
__device__ int g_cur0[NMAX], g_cur1[NMAX];
__device__ float g_ns0[NMAX], g_nd0[NMAX], g_ns1[NMAX], g_nd1[NMAX];
__device__ int g_part[2][SBLOCKS_MAX];
__device__ int g_pscan[2][SBLOCKS_MAX];
// W transposed + bf16 hi/lo split scratch: [HID rows][K<=256], K-contiguous
__device__ __align__(16) __nv_bfloat16 g_wHi[HID * 256];
__device__ __align__(16) __nv_bfloat16 g_wLo[HID * 256];

// ---------------- helpers ---------------------------------------------------
__device__ __forceinline__ uint32_t smem_u32(const void* p) {
    uint32_t a;
    asm("{ .reg .u64 t; cvta.to.shared.u64 t, %1; cvt.u32.u64 %0, t; }"
        : "=r"(a) : "l"(p));
    return a;
}

__device__ __forceinline__ uint32_t b2u(__nv_bfloat162 h) {
    return *reinterpret_cast<uint32_t*>(&h);
}

// split 2 floats into packed hi bf16x2 and lo bf16x2 (compensated)
__device__ __forceinline__ void split2(float a, float b, uint32_t& hi, uint32_t& lo) {
    __nv_bfloat162 h = __float22bfloat162_rn(make_float2(a, b));
    float la = a - __low2float(h);
    float lb = b - __high2float(h);
    __nv_bfloat162 l = __float22bfloat162_rn(make_float2(la, lb));
    hi = b2u(h);
    lo = b2u(l);
}

#define LDSM4(r, addr) \
    asm volatile("ldmatrix.sync.aligned.m8n8.x4.shared.b16 {%0,%1,%2,%3}, [%4];" \
                 : "=r"((r)[0]), "=r"((r)[1]), "=r"((r)[2]), "=r"((r)[3]) \
                 : "r"(addr))

#define MMA16816(d, a, b0, b1) \
    asm volatile("mma.sync.aligned.m16n8k16.row.col.f32.bf16.bf16.f32 " \
                 "{%0,%1,%2,%3}, {%4,%5,%6,%7}, {%8,%9}, {%0,%1,%2,%3};" \
                 : "+f"((d)[0]), "+f"((d)[1]), "+f"((d)[2]), "+f"((d)[3]) \
                 : "r"((a)[0]), "r"((a)[1]), "r"((a)[2]), "r"((a)[3]), \
                   "r"(b0), "r"(b1))

// 16B async copy global->shared; src_size=0 zero-fills (OOB guard)
__device__ __forceinline__ void cpa16(uint32_t dst, const void* src, bool full) {
    asm volatile("cp.async.cg.shared.global [%0], [%1], 16, %2;"
                 :: "r"(dst), "l"(src), "r"(full ? 16u : 0u) : "memory");
}
#define CPA_COMMIT() asm volatile("cp.async.commit_group;" ::: "memory")
#define CPA_WAIT1()  asm volatile("cp.async.wait_group 1;" ::: "memory")

// ---------------- setup kernels --------------------------------------------
__global__ void count_deg(const int* __restrict__ s0, const int* __restrict__ d0,
                          const int* __restrict__ s1, const int* __restrict__ d1, int e) {
    int i = blockIdx.x * blockDim.x + threadIdx.x;
    if (i < e) {
        atomicAdd(&g_do0[s0[i]], 1);
        atomicAdd(&g_di0[d0[i]], 1);
        atomicAdd(&g_do1[s1[i]], 1);
        atomicAdd(&g_di1[d1[i]], 1);
    }
}

__global__ void norms_k(int n) {
    int i = blockIdx.x * blockDim.x + threadIdx.x;
    if (i < n) {
        g_ns0[i] = rsqrtf(fmaxf((float)g_do0[i], 1.0f));
        g_nd0[i] = rsqrtf(fmaxf((float)g_di0[i], 1.0f));
        g_ns1[i] = rsqrtf(fmaxf((float)g_do1[i], 1.0f));
        g_nd1[i] = rsqrtf(fmaxf((float)g_di1[i], 1.0f));
    }
}

// W prep: transpose + bf16 hi/lo split.  W:[K][HID] -> wt{Hi,Lo}:[HID][K]
__global__ void w_prep(const float* __restrict__ W, int K) {
    int idx = blockIdx.x * blockDim.x + threadIdx.x;
    if (idx < K * HID) {
        int k = idx / HID, n = idx % HID;
        float w = W[idx];
        __nv_bfloat16 h = __float2bfloat16(w);
        float l = w - __bfloat162float(h);
        g_wHi[n * K + k] = h;
        g_wLo[n * K + k] = __float2bfloat16(l);
    }
}

// x prep: split fp32 x into bf16 hi/lo planes (same layout)
__global__ void x_prep(const float* __restrict__ x,
                       __nv_bfloat16* __restrict__ xHi,
                       __nv_bfloat16* __restrict__ xLo, int total4) {
    int i = blockIdx.x * blockDim.x + threadIdx.x;
    if (i < total4) {
        float4 v = *reinterpret_cast<const float4*>(x + (size_t)i * 4);
        uint32_t h0, l0, h1, l1;
        split2(v.x, v.y, h0, l0);
        split2(v.z, v.w, h1, l1);
        *reinterpret_cast<uint2*>(xHi + (size_t)i * 4) = make_uint2(h0, h1);
        *reinterpret_cast<uint2*>(xLo + (size_t)i * 4) = make_uint2(l0, l1);
    }
}

// ---------------- grid-wide exclusive scan (3 passes, 2 arrays batched) ----
__global__ void scan_pass1(const int* __restrict__ dA, const int* __restrict__ dB, int n) {
    const int* deg = blockIdx.y ? dB : dA;
    __shared__ int sh[256];
    int base = blockIdx.x * SCHUNK + threadIdx.x * 4;
    int s = 0;
#pragma unroll
    for (int q = 0; q < 4; ++q)
        if (base + q < n) s += deg[base + q];
    sh[threadIdx.x] = s;
    __syncthreads();
#pragma unroll
    for (int off = 128; off > 0; off >>= 1) {
        if (threadIdx.x < off) sh[threadIdx.x] += sh[threadIdx.x + off];
        __syncthreads();
    }
    if (threadIdx.x == 0) g_part[blockIdx.y][blockIdx.x] = sh[0];
}

__global__ void scan_pass2(int* __restrict__ rsA, int* __restrict__ rsB,
                           int nblocks, int n) {
    __shared__ int sh[2][SBLOCKS_MAX];
    int a = threadIdx.x >> 7;
    int j = threadIdx.x & 127;
    int v = (j < nblocks) ? g_part[a][j] : 0;
    sh[a][j] = v;
    __syncthreads();
#pragma unroll
    for (int off = 1; off < SBLOCKS_MAX; off <<= 1) {
        int t = (j >= off) ? sh[a][j - off] : 0;
        __syncthreads();
        sh[a][j] += t;
        __syncthreads();
    }
    if (j < nblocks) g_pscan[a][j] = sh[a][j] - v;   // exclusive
    if (j == 127) {
        int total = sh[a][SBLOCKS_MAX - 1];
        (a ? rsB : rsA)[n] = total;
    }
}

__global__ void scan_pass3(const int* __restrict__ dA, const int* __restrict__ dB,
                           int* __restrict__ rsA, int* __restrict__ rsB, int n) {
    const int* deg = blockIdx.y ? dB : dA;
    int* rs = blockIdx.y ? rsB : rsA;
    __shared__ int sh[256];
    int base = blockIdx.x * SCHUNK + threadIdx.x * 4;
    int v[4];
    int s = 0;
#pragma unroll
    for (int q = 0; q < 4; ++q) {
        v[q] = (base + q < n) ? deg[base + q] : 0;
        s += v[q];
    }
    sh[threadIdx.x] = s;
    __syncthreads();
#pragma unroll
    for (int off = 1; off < 256; off <<= 1) {
        int t = (threadIdx.x >= off) ? sh[threadIdx.x - off] : 0;
        __syncthreads();
        sh[threadIdx.x] += t;
        __syncthreads();
    }
    int ex = sh[threadIdx.x] - s + g_pscan[blockIdx.y][blockIdx.x];
#pragma unroll
    for (int q = 0; q < 4; ++q) {
        if (base + q < n) { rs[base + q] = ex; ex += v[q]; }
    }
}

__global__ void fill_csr(const int* __restrict__ src, const int* __restrict__ dst,
                         const int* __restrict__ rs, int* __restrict__ cur,
                         int* __restrict__ eidx, int e) {
    int i = blockIdx.x * blockDim.x + threadIdx.x;
    if (i < e) {
        int d = dst[i];
        int p = atomicAdd(&cur[d], 1);
        eidx[rs[d] + p] = src[i];
    }
}

// ============== pipelined mma.sync bf16x3 GEMM ==============================
// Block: 256 threads = 8 warps (4 m x 2 n), tile 128x128, K-chunk 32,
// cp.async double-buffered SMEM, 2 CTAs/SM (80 KB/CTA).
// Rows padded to 80 B -> conflict-free ldmatrix (granule perm mod 8).
#define ROWB 80
#define PLANEB (128 * ROWB)           // 10240 B
#define OFF_AHI 0
#define OFF_ALO (1 * PLANEB)
#define OFF_WHI (2 * PLANEB)
#define OFF_WLO (3 * PLANEB)
#define BUFB    (4 * PLANEB)          // 40960 B per buffer
#define GSMEMP  (2 * BUFB)            // 81920 B

struct WarpCtx {
    uint32_t aHiOff, aLoOff, wHiOff, wLoOff;
    int warp_m, warp_n, lane;
};

__device__ __forceinline__ WarpCtx mk_ctx(int tid) {
    WarpCtx c;
    int wid = tid >> 5;
    c.lane = tid & 31;
    c.warp_m = wid & 3;
    c.warp_n = wid >> 2;
    const int q4 = c.lane >> 3, lr = c.lane & 7;
    const uint32_t laneA = (uint32_t)(((q4 & 1) * 8 + lr) * ROWB + (q4 >> 1) * 16);
    const uint32_t laneB = (uint32_t)(((q4 >> 1) * 8 + lr) * ROWB + (q4 & 1) * 16);
    c.aHiOff = OFF_AHI + (uint32_t)(c.warp_m * 32) * ROWB + laneA;
    c.aLoOff = OFF_ALO + (uint32_t)(c.warp_m * 32) * ROWB + laneA;
    c.wHiOff = OFF_WHI + (uint32_t)(c.warp_n * 64) * ROWB + laneB;
    c.wLoOff = OFF_WLO + (uint32_t)(c.warp_n * 64) * ROWB + laneB;
    return c;
}

// stage one K=32 chunk: 4 planes x 128 rows x 4 granules(16B) = 2048 cp.async
// = 8 per thread.
template <int K>
__device__ __forceinline__ void stage_chunk(uint32_t base,
                                            const __nv_bfloat16* __restrict__ aHi,
                                            const __nv_bfloat16* __restrict__ aLo,
                                            const __nv_bfloat16* __restrict__ whi,
                                            const __nv_bfloat16* __restrict__ wlo,
                                            int kc, int block_m, int M, int tid) {
#pragma unroll
    for (int i = 0; i < 8; ++i) {
        int idx = tid + i * 256;          // 0..2047
        int plane = idx >> 9;             // 0..3
        int p = idx & 511;
        int r = p >> 2;                   // 0..127
        int g = p & 3;                    // granule
        uint32_t dst = base + (uint32_t)(plane * PLANEB + r * ROWB + g * 16);
        if (plane < 2) {
            int gm = block_m + r;
            bool ok = gm < M;
            size_t go = ok ? ((size_t)gm * K + kc + g * 8) : 0;
            cpa16(dst, (plane ? aLo : aHi) + go, ok);
        } else {
            size_t go = (size_t)r * K + kc + g * 8;
            cpa16(dst, (plane == 2 ? whi : wlo) + go, true);
        }
    }
}

__device__ __forceinline__ void compute_chunk(uint32_t base, const WarpCtx& c,
                                              float acc[2][8][4]) {
#pragma unroll
    for (int ks = 0; ks < 2; ++ks) {
        uint32_t ahi[2][4], alo[2][4];
#pragma unroll
        for (int ma = 0; ma < 2; ++ma) {
            uint32_t ao = (uint32_t)(ma * 16 * ROWB + ks * 32);
            LDSM4(ahi[ma], base + c.aHiOff + ao);
            LDSM4(alo[ma], base + c.aLoOff + ao);
        }
#pragma unroll
        for (int nb = 0; nb < 4; ++nb) {
            uint32_t bhi[4], blo[4];
            uint32_t bo = (uint32_t)(nb * 16 * ROWB + ks * 32);
            LDSM4(bhi, base + c.wHiOff + bo);
            LDSM4(blo, base + c.wLoOff + bo);
#pragma unroll
            for (int ma = 0; ma < 2; ++ma) {
                MMA16816(acc[ma][nb * 2 + 0], ahi[ma], bhi[0], bhi[1]);
                MMA16816(acc[ma][nb * 2 + 0], ahi[ma], blo[0], blo[1]);
                MMA16816(acc[ma][nb * 2 + 0], alo[ma], bhi[0], bhi[1]);
                MMA16816(acc[ma][nb * 2 + 1], ahi[ma], bhi[2], bhi[3]);
                MMA16816(acc[ma][nb * 2 + 1], ahi[ma], blo[2], blo[3]);
                MMA16816(acc[ma][nb * 2 + 1], alo[ma], bhi[2], bhi[3]);
            }
        }
    }
}

// MODE 0: out = planes(acc + bias)   (embed)
// MODE 1: out = fp16(acc * rowscale) (layers)
template <int K, int MODE>
__global__ __launch_bounds__(256, 2)
void gemm_pipe(const __nv_bfloat16* __restrict__ aHi,
               const __nv_bfloat16* __restrict__ aLo,
               const __nv_bfloat16* __restrict__ whi,
               const __nv_bfloat16* __restrict__ wlo,
               const float* __restrict__ bias, const float* __restrict__ rowscale,
               __nv_bfloat16* __restrict__ outHi, __nv_bfloat16* __restrict__ outLo,
               __half* __restrict__ outH, int M) {
    extern __shared__ char sm[];
    const uint32_t smb = smem_u32(sm);
    const int tid = threadIdx.x;
    const int block_m = blockIdx.x * 128;
    WarpCtx c = mk_ctx(tid);

    float acc[2][8][4];
#pragma unroll
    for (int i = 0; i < 2; ++i)
#pragma unroll
        for (int j = 0; j < 8; ++j)
#pragma unroll
            for (int q = 0; q < 4; ++q) acc[i][j][q] = 0.0f;

    constexpr int NC = K / 32;
    stage_chunk<K>(smb, aHi, aLo, whi, wlo, 0, block_m, M, tid);
    CPA_COMMIT();
#pragma unroll
    for (int ch = 0; ch < NC; ++ch) {
        if (ch + 1 < NC)
            stage_chunk<K>(smb + ((ch + 1) & 1) * BUFB, aHi, aLo, whi, wlo,
                           (ch + 1) * 32, block_m, M, tid);
        CPA_COMMIT();          // uniform: one group per iteration
        CPA_WAIT1();           // chunk ch's group complete
        __syncthreads();
        compute_chunk(smb + (ch & 1) * BUFB, c, acc);
        __syncthreads();       // buffer reads done before re-stage (2 buffers)
    }

    // ---- epilogue ----
    const int g = c.lane >> 2, t = c.lane & 3;
#pragma unroll
    for (int ma = 0; ma < 2; ++ma) {
        int r0 = block_m + c.warp_m * 32 + ma * 16 + g;
        int r1 = r0 + 8;
        float rs0 = 1.f, rs1 = 1.f;
        if (MODE == 1) {
            rs0 = (r0 < M) ? rowscale[r0] : 0.f;
            rs1 = (r1 < M) ? rowscale[r1] : 0.f;
        }
#pragma unroll
        for (int na = 0; na < 8; ++na) {
            int col = c.warp_n * 64 + na * 8 + t * 2;
            if (MODE == 0) {
                float2 bv = *reinterpret_cast<const float2*>(bias + col);
                if (r0 < M) {
                    uint32_t h, l;
                    split2(acc[ma][na][0] + bv.x, acc[ma][na][1] + bv.y, h, l);
                    *reinterpret_cast<uint32_t*>(outHi + (size_t)r0 * HID + col) = h;
                    *reinterpret_cast<uint32_t*>(outLo + (size_t)r0 * HID + col) = l;
                }
                if (r1 < M) {
                    uint32_t h, l;
                    split2(acc[ma][na][2] + bv.x, acc[ma][na][3] + bv.y, h, l);
                    *reinterpret_cast<uint32_t*>(outHi + (size_t)r1 * HID + col) = h;
                    *reinterpret_cast<uint32_t*>(outLo + (size_t)r1 * HID + col) = l;
                }
            } else {
                if (r0 < M) {
                    __half2 o = __floats2half2_rn(acc[ma][na][0] * rs0, acc[ma][na][1] * rs0);
                    *reinterpret_cast<__half2*>(outH + (size_t)r0 * HID + col) = o;
                }
                if (r1 < M) {
                    __half2 o = __floats2half2_rn(acc[ma][na][2] * rs1, acc[ma][na][3] * rs1);
                    *reinterpret_cast<__half2*>(outH + (size_t)r1 * HID + col) = o;
                }
            }
        }
    }
}

// ---------------- CSR aggregation + fused epilogues ------------------------
__device__ __forceinline__ float4 agg_core(const int* __restrict__ eidx,
                                           const __half* __restrict__ B,
                                           int beg, int end, int lane) {
    float4 a0 = make_float4(0.f, 0.f, 0.f, 0.f);
    float4 a1 = make_float4(0.f, 0.f, 0.f, 0.f);
    const int co = lane * 4;
    int i = beg;
    for (; i + 3 < end; i += 4) {
        int s0 = eidx[i], s1 = eidx[i + 1], s2 = eidx[i + 2], s3 = eidx[i + 3];
        uint2 u0 = *reinterpret_cast<const uint2*>(B + (size_t)s0 * HID + co);
        uint2 u1 = *reinterpret_cast<const uint2*>(B + (size_t)s1 * HID + co);
        uint2 u2 = *reinterpret_cast<const uint2*>(B + (size_t)s2 * HID + co);
        uint2 u3 = *reinterpret_cast<const uint2*>(B + (size_t)s3 * HID + co);
        float2 f;
        f = __half22float2(*reinterpret_cast<__half2*>(&u0.x)); a0.x += f.x; a0.y += f.y;
        f = __half22float2(*reinterpret_cast<__half2*>(&u0.y)); a0.z += f.x; a0.w += f.y;
        f = __half22float2(*reinterpret_cast<__half2*>(&u1.x)); a1.x += f.x; a1.y += f.y;
        f = __half22float2(*reinterpret_cast<__half2*>(&u1.y)); a1.z += f.x; a1.w += f.y;
        f = __half22float2(*reinterpret_cast<__half2*>(&u2.x)); a0.x += f.x; a0.y += f.y;
        f = __half22float2(*reinterpret_cast<__half2*>(&u2.y)); a0.z += f.x; a0.w += f.y;
        f = __half22float2(*reinterpret_cast<__half2*>(&u3.x)); a1.x += f.x; a1.y += f.y;
        f = __half22float2(*reinterpret_cast<__half2*>(&u3.y)); a1.z += f.x; a1.w += f.y;
    }
    for (; i < end; ++i) {
        int s0 = eidx[i];
        uint2 u0 = *reinterpret_cast<const uint2*>(B + (size_t)s0 * HID + co);
        float2 f;
        f = __half22float2(*reinterpret_cast<__half2*>(&u0.x)); a0.x += f.x; a0.y += f.y;
        f = __half22float2(*reinterpret_cast<__half2*>(&u0.y)); a0.z += f.x; a0.w += f.y;
    }
    a0.x += a1.x; a0.y += a1.y; a0.z += a1.z; a0.w += a1.w;
    return a0;
}

__global__ void agg_relu_planes(const int* __restrict__ eidx, const int* __restrict__ rs,
                                const __half* __restrict__ B, const float* __restrict__ nd,
                                const float* __restrict__ bias,
                                __nv_bfloat16* __restrict__ outHi,
                                __nv_bfloat16* __restrict__ outLo, int n) {
    int t = blockIdx.x * blockDim.x + threadIdx.x;
    int v = t >> 5;
    int lane = t & 31;
    if (v >= n) return;
    float4 acc = agg_core(eidx, B, rs[v], rs[v + 1], lane);
    float d = nd[v];
    float4 bv = *reinterpret_cast<const float4*>(bias + lane * 4);
    float o0 = fmaxf(fmaf(acc.x, d, bv.x), 0.f);
    float o1 = fmaxf(fmaf(acc.y, d, bv.y), 0.f);
    float o2 = fmaxf(fmaf(acc.z, d, bv.z), 0.f);
    float o3 = fmaxf(fmaf(acc.w, d, bv.w), 0.f);
    uint32_t h0, l0, h1, l1;
    split2(o0, o1, h0, l0);
    split2(o2, o3, h1, l1);
    size_t base = (size_t)v * HID + lane * 4;
    *reinterpret_cast<uint2*>(outHi + base) = make_uint2(h0, h1);
    *reinterpret_cast<uint2*>(outLo + base) = make_uint2(l0, l1);
}

__global__ void agg_relu_out(const int* __restrict__ eidx, const int* __restrict__ rs,
                             const __half* __restrict__ B, const float* __restrict__ nd,
                             const float* __restrict__ bias, float* __restrict__ out, int n) {
    int t = blockIdx.x * blockDim.x + threadIdx.x;
    int v = t >> 5;
    int lane = t & 31;
    if (v >= n) return;
    float4 acc = agg_core(eidx, B, rs[v], rs[v + 1], lane);
    float d = nd[v];
    float4 bv = *reinterpret_cast<const float4*>(bias + lane * 4);
    float4 o;
    o.x = fmaxf(fmaf(acc.x, d, bv.x), 0.f);
    o.y = fmaxf(fmaf(acc.y, d, bv.y), 0.f);
    o.z = fmaxf(fmaf(acc.z, d, bv.z), 0.f);
    o.w = fmaxf(fmaf(acc.w, d, bv.w), 0.f);
    *reinterpret_cast<float4*>(out + (size_t)v * HID + lane * 4) = o;
}

// ---------------- launch ----------------------------------------------------
extern "C" void kernel_launch(void* const* d_in, const int* in_sizes, int n_in,
                              void* d_out, int out_size) {
    const float* x  = (const float*)d_in[0];
    const float* We = (const float*)d_in[1];
    const float* be = (const float*)d_in[2];
    const float* W1 = (const float*)d_in[3];
    const float* b1 = (const float*)d_in[4];
    const float* W2 = (const float*)d_in[5];
    const float* b2 = (const float*)d_in[6];
    const int* src0 = (const int*)d_in[7];
    const int* dst0 = (const int*)d_in[8];
    const int* src1 = (const int*)d_in[9];
    const int* dst1 = (const int*)d_in[10];

    int n = in_sizes[0] / INF;
    int e = in_sizes[7];

    static bool attr_done = false;
    if (!attr_done) {
        cudaFuncSetAttribute(gemm_pipe<256, 0>, cudaFuncAttributeMaxDynamicSharedMemorySize, GSMEMP);
        cudaFuncSetAttribute(gemm_pipe<128, 1>, cudaFuncAttributeMaxDynamicSharedMemorySize, GSMEMP);
        attr_done = true;
    }

    float *pns0, *pnd0, *pns1, *pnd1;
    int *prs0, *prs1, *pe0, *pe1, *pc0, *pc1;
    int *pdo0, *pdi0, *pdo1, *pdi1;
    __nv_bfloat16 *pwHi, *pwLo, *paHi, *paLo, *pxHi, *pxLo;
    __half *pH;
    cudaGetSymbolAddress((void**)&pH,   g_bufH);
    cudaGetSymbolAddress((void**)&paHi, g_aHi);
    cudaGetSymbolAddress((void**)&paLo, g_aLo);
    cudaGetSymbolAddress((void**)&pxHi, g_xHi);
    cudaGetSymbolAddress((void**)&pxLo, g_xLo);
    cudaGetSymbolAddress((void**)&pns0, g_ns0);
    cudaGetSymbolAddress((void**)&pnd0, g_nd0);
    cudaGetSymbolAddress((void**)&pns1, g_ns1);
    cudaGetSymbolAddress((void**)&pnd1, g_nd1);
    cudaGetSymbolAddress((void**)&prs0, g_rs0);
    cudaGetSymbolAddress((void**)&prs1, g_rs1);
    cudaGetSymbolAddress((void**)&pe0,  g_eidx0);
    cudaGetSymbolAddress((void**)&pe1,  g_eidx1);
    cudaGetSymbolAddress((void**)&pc0,  g_cur0);
    cudaGetSymbolAddress((void**)&pc1,  g_cur1);
    cudaGetSymbolAddress((void**)&pdo0, g_do0);
    cudaGetSymbolAddress((void**)&pdi0, g_di0);
    cudaGetSymbolAddress((void**)&pdo1, g_do1);
    cudaGetSymbolAddress((void**)&pdi1, g_di1);
    cudaGetSymbolAddress((void**)&pwHi, g_wHi);
    cudaGetSymbolAddress((void**)&pwLo, g_wLo);

    int nb = (n + 255) / 256;
    int eb = (e + 255) / 256;
    int gb = (n + 127) / 128;
    long agg_threads = (long)n * 32;
    int ab = (int)((agg_threads + 255) / 256);
    int snb = (n + SCHUNK - 1) / SCHUNK;
    int x4 = n * INF / 4;

    // --- zero degree/cursor arrays via memset nodes (graph-capturable) ---
    cudaMemsetAsync(pdo0, 0, (size_t)n * sizeof(int));
    cudaMemsetAsync(pdi0, 0, (size_t)n * sizeof(int));
    cudaMemsetAsync(pdo1, 0, (size_t)n * sizeof(int));
    cudaMemsetAsync(pdi1, 0, (size_t)n * sizeof(int));
    cudaMemsetAsync(pc0,  0, (size_t)n * sizeof(int));
    cudaMemsetAsync(pc1,  0, (size_t)n * sizeof(int));

    // --- graph prep: degrees, norms, CSR-by-dst for both layers ---
    count_deg<<<eb, 256>>>(src0, dst0, src1, dst1, e);
    norms_k<<<nb, 256>>>(n);
    {
        dim3 sg(snb, 2);
        scan_pass1<<<sg, 256>>>(pdi0, pdi1, n);
        scan_pass2<<<1, 256>>>(prs0, prs1, snb, n);
        scan_pass3<<<sg, 256>>>(pdi0, pdi1, prs0, prs1, n);
    }
    fill_csr<<<eb, 256>>>(src0, dst0, prs0, pc0, pe0, e);
    fill_csr<<<eb, 256>>>(src1, dst1, prs1, pc1, pe1, e);

    // --- embed: planes(A) = x @ We + be ---
    x_prep<<<(x4 + 255) / 256, 256>>>(x, pxHi, pxLo, x4);
    w_prep<<<(256 * HID + 255) / 256, 256>>>(We, 256);
    gemm_pipe<256, 0><<<gb, 256, GSMEMP>>>(pxHi, pxLo, pwHi, pwLo, be, nullptr,
                                           paHi, paLo, nullptr, n);

    // --- layer 1: bufH = fp16((planes @ W1) * ns0) ; planes = relu(agg*nd0 + b1) ---
    w_prep<<<(128 * HID + 255) / 256, 256>>>(W1, 128);
    gemm_pipe<128, 1><<<gb, 256, GSMEMP>>>(paHi, paLo, pwHi, pwLo, nullptr, pns0,
                                           nullptr, nullptr, pH, n);
    agg_relu_planes<<<ab, 256>>>(pe0, prs0, pH, pnd0, b1, paHi, paLo, n);

    // --- layer 2: bufH = fp16((planes @ W2) * ns1) ; out = relu(agg*nd1 + b2) ---
    w_prep<<<(128 * HID + 255) / 256, 256>>>(W2, 128);
    gemm_pipe<128, 1><<<gb, 256, GSMEMP>>>(paHi, paLo, pwHi, pwLo, nullptr, pns1,
                                           nullptr, nullptr, pH, n);
    agg_relu_out<<<ab, 256>>>(pe1, prs1, pH, pnd1, b2, (float*)d_out, n);
}

// round 13
// speedup vs baseline: 1.2258x; 1.1786x over previous
#include <cuda_runtime.h>
#include <cuda_bf16.h>
#include <cuda_fp16.h>
#include <cstdint>

// Problem-fixed maxima (sizes also derived at runtime from in_sizes)
#define NMAX 100000
#define EMAX 1600000
#define HID  128
#define INF  256

#define SCHUNK 1024
#define SBLOCKS_MAX 128   // ceil(NMAX/SCHUNK)=98 <= 128

// ---------------- scratch (device globals: no allocation allowed) ----------
__device__ __align__(256) __half g_bufH[(size_t)NMAX * HID];          // gathered GEMM out
__device__ __align__(256) __nv_bfloat16 g_aHi[(size_t)NMAX * HID];    // A hi plane
__device__ __align__(256) __nv_bfloat16 g_aLo[(size_t)NMAX * HID];    // A lo plane
__device__ __align__(16)  int   g_eidx0[EMAX];
__device__ __align__(16)  int   g_eidx1[EMAX];
__device__ __align__(16)  int   g_rs0[NMAX + 1];
__device__ __align__(16)  int   g_rs1[NMAX + 1];
__device__ int g_do0[NMAX], g_di0[NMAX], g_do1[NMAX], g_di1[NMAX];
__device__ int g_cur0[NMAX], g_cur1[NMAX];
__device__ float g_ns0[NMAX], g_nd0[NMAX], g_ns1[NMAX], g_nd1[NMAX];
__device__ int g_part[2][SBLOCKS_MAX];
__device__ int g_pscan[2][SBLOCKS_MAX];
// W transposed + bf16 hi/lo split scratch: [HID rows][K<=256], K-contiguous
__device__ __align__(16) __nv_bfloat16 g_wHi[HID * 256];
__device__ __align__(16) __nv_bfloat16 g_wLo[HID * 256];

// ---------------- helpers ---------------------------------------------------
__device__ __forceinline__ uint32_t smem_u32(const void* p) {
    uint32_t a;
    asm("{ .reg .u64 t; cvta.to.shared.u64 t, %1; cvt.u32.u64 %0, t; }"
        : "=r"(a) : "l"(p));
    return a;
}

__device__ __forceinline__ uint32_t b2u(__nv_bfloat162 h) {
    return *reinterpret_cast<uint32_t*>(&h);
}

// split 2 floats into packed hi bf16x2 and lo bf16x2 (compensated)
__device__ __forceinline__ void split2(float a, float b, uint32_t& hi, uint32_t& lo) {
    __nv_bfloat162 h = __float22bfloat162_rn(make_float2(a, b));
    float la = a - __low2float(h);
    float lb = b - __high2float(h);
    __nv_bfloat162 l = __float22bfloat162_rn(make_float2(la, lb));
    hi = b2u(h);
    lo = b2u(l);
}

#define LDSM4(r, addr) \
    asm volatile("ldmatrix.sync.aligned.m8n8.x4.shared.b16 {%0,%1,%2,%3}, [%4];" \
                 : "=r"((r)[0]), "=r"((r)[1]), "=r"((r)[2]), "=r"((r)[3]) \
                 : "r"(addr))

#define MMA16816(d, a, b0, b1) \
    asm volatile("mma.sync.aligned.m16n8k16.row.col.f32.bf16.bf16.f32 " \
                 "{%0,%1,%2,%3}, {%4,%5,%6,%7}, {%8,%9}, {%0,%1,%2,%3};" \
                 : "+f"((d)[0]), "+f"((d)[1]), "+f"((d)[2]), "+f"((d)[3]) \
                 : "r"((a)[0]), "r"((a)[1]), "r"((a)[2]), "r"((a)[3]), \
                   "r"(b0), "r"(b1))

// ---------------- setup kernels --------------------------------------------
__global__ void count_deg(const int* __restrict__ s0, const int* __restrict__ d0,
                          const int* __restrict__ s1, const int* __restrict__ d1, int e) {
    int i = blockIdx.x * blockDim.x + threadIdx.x;
    if (i < e) {
        atomicAdd(&g_do0[s0[i]], 1);
        atomicAdd(&g_di0[d0[i]], 1);
        atomicAdd(&g_do1[s1[i]], 1);
        atomicAdd(&g_di1[d1[i]], 1);
    }
}

__global__ void norms_k(int n) {
    int i = blockIdx.x * blockDim.x + threadIdx.x;
    if (i < n) {
        g_ns0[i] = rsqrtf(fmaxf((float)g_do0[i], 1.0f));
        g_nd0[i] = rsqrtf(fmaxf((float)g_di0[i], 1.0f));
        g_ns1[i] = rsqrtf(fmaxf((float)g_do1[i], 1.0f));
        g_nd1[i] = rsqrtf(fmaxf((float)g_di1[i], 1.0f));
    }
}

// W prep: transpose + bf16 hi/lo split.  W:[K][HID] -> wt{Hi,Lo}:[HID][K]
__global__ void w_prep(const float* __restrict__ W, int K) {
    int idx = blockIdx.x * blockDim.x + threadIdx.x;
    if (idx < K * HID) {
        int k = idx / HID, n = idx % HID;
        float w = W[idx];
        __nv_bfloat16 h = __float2bfloat16(w);
        float l = w - __bfloat162float(h);
        g_wHi[n * K + k] = h;
        g_wLo[n * K + k] = __float2bfloat16(l);
    }
}

// ---------------- grid-wide exclusive scan (3 passes, 2 arrays batched) ----
__global__ void scan_pass1(const int* __restrict__ dA, const int* __restrict__ dB, int n) {
    const int* deg = blockIdx.y ? dB : dA;
    __shared__ int sh[256];
    int base = blockIdx.x * SCHUNK + threadIdx.x * 4;
    int s = 0;
#pragma unroll
    for (int q = 0; q < 4; ++q)
        if (base + q < n) s += deg[base + q];
    sh[threadIdx.x] = s;
    __syncthreads();
#pragma unroll
    for (int off = 128; off > 0; off >>= 1) {
        if (threadIdx.x < off) sh[threadIdx.x] += sh[threadIdx.x + off];
        __syncthreads();
    }
    if (threadIdx.x == 0) g_part[blockIdx.y][blockIdx.x] = sh[0];
}

__global__ void scan_pass2(int* __restrict__ rsA, int* __restrict__ rsB,
                           int nblocks, int n) {
    __shared__ int sh[2][SBLOCKS_MAX];
    int a = threadIdx.x >> 7;
    int j = threadIdx.x & 127;
    int v = (j < nblocks) ? g_part[a][j] : 0;
    sh[a][j] = v;
    __syncthreads();
#pragma unroll
    for (int off = 1; off < SBLOCKS_MAX; off <<= 1) {
        int t = (j >= off) ? sh[a][j - off] : 0;
        __syncthreads();
        sh[a][j] += t;
        __syncthreads();
    }
    if (j < nblocks) g_pscan[a][j] = sh[a][j] - v;   // exclusive
    if (j == 127) {
        int total = sh[a][SBLOCKS_MAX - 1];
        (a ? rsB : rsA)[n] = total;
    }
}

__global__ void scan_pass3(const int* __restrict__ dA, const int* __restrict__ dB,
                           int* __restrict__ rsA, int* __restrict__ rsB, int n) {
    const int* deg = blockIdx.y ? dB : dA;
    int* rs = blockIdx.y ? rsB : rsA;
    __shared__ int sh[256];
    int base = blockIdx.x * SCHUNK + threadIdx.x * 4;
    int v[4];
    int s = 0;
#pragma unroll
    for (int q = 0; q < 4; ++q) {
        v[q] = (base + q < n) ? deg[base + q] : 0;
        s += v[q];
    }
    sh[threadIdx.x] = s;
    __syncthreads();
#pragma unroll
    for (int off = 1; off < 256; off <<= 1) {
        int t = (threadIdx.x >= off) ? sh[threadIdx.x - off] : 0;
        __syncthreads();
        sh[threadIdx.x] += t;
        __syncthreads();
    }
    int ex = sh[threadIdx.x] - s + g_pscan[blockIdx.y][blockIdx.x];
#pragma unroll
    for (int q = 0; q < 4; ++q) {
        if (base + q < n) { rs[base + q] = ex; ex += v[q]; }
    }
}

__global__ void fill_csr(const int* __restrict__ src, const int* __restrict__ dst,
                         const int* __restrict__ rs, int* __restrict__ cur,
                         int* __restrict__ eidx, int e) {
    int i = blockIdx.x * blockDim.x + threadIdx.x;
    if (i < e) {
        int d = dst[i];
        int p = atomicAdd(&cur[d], 1);
        eidx[rs[d] + p] = src[i];
    }
}

// ============== mma.sync bf16x3 GEMM (R9 structure: best measured) ==========
// Block: 256 threads = 8 warps (4 m x 2 n), tile 128x128, K-chunk 64 in SMEM.
// SMEM rows padded to 144 B -> conflict-free ldmatrix. 2 CTAs/SM.
#define ROWB 144
#define OFF_AHI 0
#define OFF_ALO (128 * ROWB)
#define OFF_WHI (2 * 128 * ROWB)
#define OFF_WLO (3 * 128 * ROWB)
#define GSMEM   (4 * 128 * ROWB)      // 73728 B

struct WarpCtx {
    uint32_t aHiBase, aLoBase, wHiBase, wLoBase;
    int warp_m, warp_n, lane;
};

__device__ __forceinline__ WarpCtx mk_ctx(uint32_t smb, int tid) {
    WarpCtx c;
    int wid = tid >> 5;
    c.lane = tid & 31;
    c.warp_m = wid & 3;
    c.warp_n = wid >> 2;
    const int q4 = c.lane >> 3, lr = c.lane & 7;
    const uint32_t laneA = (uint32_t)(((q4 & 1) * 8 + lr) * ROWB + (q4 >> 1) * 16);
    const uint32_t laneB = (uint32_t)(((q4 >> 1) * 8 + lr) * ROWB + (q4 & 1) * 16);
    c.aHiBase = smb + OFF_AHI + (uint32_t)(c.warp_m * 32) * ROWB + laneA;
    c.aLoBase = smb + OFF_ALO + (uint32_t)(c.warp_m * 32) * ROWB + laneA;
    c.wHiBase = smb + OFF_WHI + (uint32_t)(c.warp_n * 64) * ROWB + laneB;
    c.wLoBase = smb + OFF_WLO + (uint32_t)(c.warp_n * 64) * ROWB + laneB;
    return c;
}

__device__ __forceinline__ void stage_w(char* sm, const __nv_bfloat16* whi,
                                        const __nv_bfloat16* wlo, int K, int kc, int tid) {
    const int cq = (tid & 7) * 8;
    const int r0 = tid >> 3;
#pragma unroll
    for (int it = 0; it < 4; ++it) {
        int r = r0 + it * 32;
        uint4 vh = *reinterpret_cast<const uint4*>(whi + (size_t)r * K + kc + cq);
        uint4 vl = *reinterpret_cast<const uint4*>(wlo + (size_t)r * K + kc + cq);
        uint32_t off = (uint32_t)(r * ROWB + cq * 2);
        *reinterpret_cast<uint4*>(sm + OFF_WHI + off) = vh;
        *reinterpret_cast<uint4*>(sm + OFF_WLO + off) = vl;
    }
}

__device__ __forceinline__ void compute_chunk(uint32_t smb, const WarpCtx& c,
                                              float acc[2][8][4]) {
#pragma unroll
    for (int ks = 0; ks < 4; ++ks) {
        uint32_t ahi[2][4], alo[2][4];
#pragma unroll
        for (int ma = 0; ma < 2; ++ma) {
            uint32_t ao = (uint32_t)(ma * 16 * ROWB + ks * 32);
            LDSM4(ahi[ma], c.aHiBase + ao);
            LDSM4(alo[ma], c.aLoBase + ao);
        }
#pragma unroll
        for (int nb = 0; nb < 4; ++nb) {
            uint32_t bhi[4], blo[4];
            uint32_t bo = (uint32_t)(nb * 16 * ROWB + ks * 32);
            LDSM4(bhi, c.wHiBase + bo);
            LDSM4(blo, c.wLoBase + bo);
#pragma unroll
            for (int ma = 0; ma < 2; ++ma) {
                MMA16816(acc[ma][nb * 2 + 0], ahi[ma], bhi[0], bhi[1]);
                MMA16816(acc[ma][nb * 2 + 0], ahi[ma], blo[0], blo[1]);
                MMA16816(acc[ma][nb * 2 + 0], alo[ma], bhi[0], bhi[1]);
                MMA16816(acc[ma][nb * 2 + 1], ahi[ma], bhi[2], bhi[3]);
                MMA16816(acc[ma][nb * 2 + 1], ahi[ma], blo[2], blo[3]);
                MMA16816(acc[ma][nb * 2 + 1], alo[ma], bhi[2], bhi[3]);
            }
        }
    }
}

// ---- EMBED GEMM: A = x fp32 [M][256] (split in staging), out = planes ----
__global__ __launch_bounds__(256, 2)
void gemm_embed(const float* __restrict__ A,
                const __nv_bfloat16* __restrict__ whi,
                const __nv_bfloat16* __restrict__ wlo,
                const float* __restrict__ bias,
                __nv_bfloat16* __restrict__ outHi,
                __nv_bfloat16* __restrict__ outLo, int M) {
    constexpr int K = 256;
    extern __shared__ char sm[];
    const uint32_t smb = smem_u32(sm);
    const int tid = threadIdx.x;
    const int block_m = blockIdx.x * 128;
    WarpCtx c = mk_ctx(smb, tid);

    float acc[2][8][4];
#pragma unroll
    for (int i = 0; i < 2; ++i)
#pragma unroll
        for (int j = 0; j < 8; ++j)
#pragma unroll
            for (int q = 0; q < 4; ++q) acc[i][j][q] = 0.0f;

#pragma unroll 1
    for (int kc = 0; kc < K; kc += 64) {
        {
            const int cq = (tid & 15) * 4;
            const int r0 = tid >> 4;
#pragma unroll
            for (int it = 0; it < 8; ++it) {
                int r = r0 + it * 16;
                int gm = block_m + r;
                float4 v = make_float4(0.f, 0.f, 0.f, 0.f);
                if (gm < M)
                    v = *reinterpret_cast<const float4*>(A + (size_t)gm * K + kc + cq);
                uint32_t h0, l0, h1, l1;
                split2(v.x, v.y, h0, l0);
                split2(v.z, v.w, h1, l1);
                uint32_t off = (uint32_t)(r * ROWB + cq * 2);
                *reinterpret_cast<uint2*>(sm + OFF_AHI + off) = make_uint2(h0, h1);
                *reinterpret_cast<uint2*>(sm + OFF_ALO + off) = make_uint2(l0, l1);
            }
        }
        stage_w(sm, whi, wlo, K, kc, tid);
        __syncthreads();
        compute_chunk(smb, c, acc);
        __syncthreads();
    }

    const int g = c.lane >> 2, t = c.lane & 3;
#pragma unroll
    for (int ma = 0; ma < 2; ++ma) {
        int r0 = block_m + c.warp_m * 32 + ma * 16 + g;
        int r1 = r0 + 8;
#pragma unroll
        for (int na = 0; na < 8; ++na) {
            int col = c.warp_n * 64 + na * 8 + t * 2;
            float2 bv = *reinterpret_cast<const float2*>(bias + col);
            if (r0 < M) {
                uint32_t h, l;
                split2(acc[ma][na][0] + bv.x, acc[ma][na][1] + bv.y, h, l);
                *reinterpret_cast<uint32_t*>(outHi + (size_t)r0 * HID + col) = h;
                *reinterpret_cast<uint32_t*>(outLo + (size_t)r0 * HID + col) = l;
            }
            if (r1 < M) {
                uint32_t h, l;
                split2(acc[ma][na][2] + bv.x, acc[ma][na][3] + bv.y, h, l);
                *reinterpret_cast<uint32_t*>(outHi + (size_t)r1 * HID + col) = h;
                *reinterpret_cast<uint32_t*>(outLo + (size_t)r1 * HID + col) = l;
            }
        }
    }
}

// ---- LAYER GEMM: A = pre-split planes [M][128]; out = fp16(acc*rowscale) ----
__global__ __launch_bounds__(256, 2)
void gemm_layer(const __nv_bfloat16* __restrict__ aHi,
                const __nv_bfloat16* __restrict__ aLo,
                const __nv_bfloat16* __restrict__ whi,
                const __nv_bfloat16* __restrict__ wlo,
                const float* __restrict__ rowscale,
                __half* __restrict__ C, int M) {
    constexpr int K = 128;
    extern __shared__ char sm[];
    const uint32_t smb = smem_u32(sm);
    const int tid = threadIdx.x;
    const int block_m = blockIdx.x * 128;
    WarpCtx c = mk_ctx(smb, tid);

    float acc[2][8][4];
#pragma unroll
    for (int i = 0; i < 2; ++i)
#pragma unroll
        for (int j = 0; j < 8; ++j)
#pragma unroll
            for (int q = 0; q < 4; ++q) acc[i][j][q] = 0.0f;

#pragma unroll 1
    for (int kc = 0; kc < K; kc += 64) {
        {
            const int cq = (tid & 7) * 8;
            const int r0 = tid >> 3;
#pragma unroll
            for (int it = 0; it < 4; ++it) {
                int r = r0 + it * 32;
                int gm = block_m + r;
                uint4 vh = make_uint4(0, 0, 0, 0), vl = make_uint4(0, 0, 0, 0);
                if (gm < M) {
                    vh = *reinterpret_cast<const uint4*>(aHi + (size_t)gm * K + kc + cq);
                    vl = *reinterpret_cast<const uint4*>(aLo + (size_t)gm * K + kc + cq);
                }
                uint32_t off = (uint32_t)(r * ROWB + cq * 2);
                *reinterpret_cast<uint4*>(sm + OFF_AHI + off) = vh;
                *reinterpret_cast<uint4*>(sm + OFF_ALO + off) = vl;
            }
        }
        stage_w(sm, whi, wlo, K, kc, tid);
        __syncthreads();
        compute_chunk(smb, c, acc);
        __syncthreads();
    }

    const int g = c.lane >> 2, t = c.lane & 3;
#pragma unroll
    for (int ma = 0; ma < 2; ++ma) {
        int r0 = block_m + c.warp_m * 32 + ma * 16 + g;
        int r1 = r0 + 8;
        float rs0 = (r0 < M) ? rowscale[r0] : 0.f;
        float rs1 = (r1 < M) ? rowscale[r1] : 0.f;
#pragma unroll
        for (int na = 0; na < 8; ++na) {
            int col = c.warp_n * 64 + na * 8 + t * 2;
            if (r0 < M) {
                __half2 o = __floats2half2_rn(acc[ma][na][0] * rs0, acc[ma][na][1] * rs0);
                *reinterpret_cast<__half2*>(C + (size_t)r0 * HID + col) = o;
            }
            if (r1 < M) {
                __half2 o = __floats2half2_rn(acc[ma][na][2] * rs1, acc[ma][na][3] * rs1);
                *reinterpret_cast<__half2*>(C + (size_t)r1 * HID + col) = o;
            }
        }
    }
}

// ---------------- CSR aggregation + fused epilogues ------------------------
__device__ __forceinline__ float4 agg_core(const int* __restrict__ eidx,
                                           const __half* __restrict__ B,
                                           int beg, int end, int lane) {
    float4 a0 = make_float4(0.f, 0.f, 0.f, 0.f);
    float4 a1 = make_float4(0.f, 0.f, 0.f, 0.f);
    const int co = lane * 4;
    int i = beg;
    for (; i + 3 < end; i += 4) {
        int s0 = eidx[i], s1 = eidx[i + 1], s2 = eidx[i + 2], s3 = eidx[i + 3];
        uint2 u0 = *reinterpret_cast<const uint2*>(B + (size_t)s0 * HID + co);
        uint2 u1 = *reinterpret_cast<const uint2*>(B + (size_t)s1 * HID + co);
        uint2 u2 = *reinterpret_cast<const uint2*>(B + (size_t)s2 * HID + co);
        uint2 u3 = *reinterpret_cast<const uint2*>(B + (size_t)s3 * HID + co);
        float2 f;
        f = __half22float2(*reinterpret_cast<__half2*>(&u0.x)); a0.x += f.x; a0.y += f.y;
        f = __half22float2(*reinterpret_cast<__half2*>(&u0.y)); a0.z += f.x; a0.w += f.y;
        f = __half22float2(*reinterpret_cast<__half2*>(&u1.x)); a1.x += f.x; a1.y += f.y;
        f = __half22float2(*reinterpret_cast<__half2*>(&u1.y)); a1.z += f.x; a1.w += f.y;
        f = __half22float2(*reinterpret_cast<__half2*>(&u2.x)); a0.x += f.x; a0.y += f.y;
        f = __half22float2(*reinterpret_cast<__half2*>(&u2.y)); a0.z += f.x; a0.w += f.y;
        f = __half22float2(*reinterpret_cast<__half2*>(&u3.x)); a1.x += f.x; a1.y += f.y;
        f = __half22float2(*reinterpret_cast<__half2*>(&u3.y)); a1.z += f.x; a1.w += f.y;
    }
    for (; i < end; ++i) {
        int s0 = eidx[i];
        uint2 u0 = *reinterpret_cast<const uint2*>(B + (size_t)s0 * HID + co);
        float2 f;
        f = __half22float2(*reinterpret_cast<__half2*>(&u0.x)); a0.x += f.x; a0.y += f.y;
        f = __half22float2(*reinterpret_cast<__half2*>(&u0.y)); a0.z += f.x; a0.w += f.y;
    }
    a0.x += a1.x; a0.y += a1.y; a0.z += a1.z; a0.w += a1.w;
    return a0;
}

__global__ void agg_relu_planes(const int* __restrict__ eidx, const int* __restrict__ rs,
                                const __half* __restrict__ B, const float* __restrict__ nd,
                                const float* __restrict__ bias,
                                __nv_bfloat16* __restrict__ outHi,
                                __nv_bfloat16* __restrict__ outLo, int n) {
    int t = blockIdx.x * blockDim.x + threadIdx.x;
    int v = t >> 5;
    int lane = t & 31;
    if (v >= n) return;
    float4 acc = agg_core(eidx, B, rs[v], rs[v + 1], lane);
    float d = nd[v];
    float4 bv = *reinterpret_cast<const float4*>(bias + lane * 4);
    float o0 = fmaxf(fmaf(acc.x, d, bv.x), 0.f);
    float o1 = fmaxf(fmaf(acc.y, d, bv.y), 0.f);
    float o2 = fmaxf(fmaf(acc.z, d, bv.z), 0.f);
    float o3 = fmaxf(fmaf(acc.w, d, bv.w), 0.f);
    uint32_t h0, l0, h1, l1;
    split2(o0, o1, h0, l0);
    split2(o2, o3, h1, l1);
    size_t base = (size_t)v * HID + lane * 4;
    *reinterpret_cast<uint2*>(outHi + base) = make_uint2(h0, h1);
    *reinterpret_cast<uint2*>(outLo + base) = make_uint2(l0, l1);
}

__global__ void agg_relu_out(const int* __restrict__ eidx, const int* __restrict__ rs,
                             const __half* __restrict__ B, const float* __restrict__ nd,
                             const float* __restrict__ bias, float* __restrict__ out, int n) {
    int t = blockIdx.x * blockDim.x + threadIdx.x;
    int v = t >> 5;
    int lane = t & 31;
    if (v >= n) return;
    float4 acc = agg_core(eidx, B, rs[v], rs[v + 1], lane);
    float d = nd[v];
    float4 bv = *reinterpret_cast<const float4*>(bias + lane * 4);
    float4 o;
    o.x = fmaxf(fmaf(acc.x, d, bv.x), 0.f);
    o.y = fmaxf(fmaf(acc.y, d, bv.y), 0.f);
    o.z = fmaxf(fmaf(acc.z, d, bv.z), 0.f);
    o.w = fmaxf(fmaf(acc.w, d, bv.w), 0.f);
    *reinterpret_cast<float4*>(out + (size_t)v * HID + lane * 4) = o;
}

// ---------------- launch ----------------------------------------------------
extern "C" void kernel_launch(void* const* d_in, const int* in_sizes, int n_in,
                              void* d_out, int out_size) {
    const float* x  = (const float*)d_in[0];
    const float* We = (const float*)d_in[1];
    const float* be = (const float*)d_in[2];
    const float* W1 = (const float*)d_in[3];
    const float* b1 = (const float*)d_in[4];
    const float* W2 = (const float*)d_in[5];
    const float* b2 = (const float*)d_in[6];
    const int* src0 = (const int*)d_in[7];
    const int* dst0 = (const int*)d_in[8];
    const int* src1 = (const int*)d_in[9];
    const int* dst1 = (const int*)d_in[10];

    int n = in_sizes[0] / INF;
    int e = in_sizes[7];

    // one-time resources (created outside any graph capture, on first
    // correctness call; no device memory involved)
    static bool init_done = false;
    static cudaStream_t s2;
    static cudaEvent_t evRoot, evNorm, evCsr;
    if (!init_done) {
        cudaFuncSetAttribute(gemm_embed, cudaFuncAttributeMaxDynamicSharedMemorySize, GSMEM);
        cudaFuncSetAttribute(gemm_layer, cudaFuncAttributeMaxDynamicSharedMemorySize, GSMEM);
        cudaStreamCreateWithFlags(&s2, cudaStreamNonBlocking);
        cudaEventCreateWithFlags(&evRoot, cudaEventDisableTiming);
        cudaEventCreateWithFlags(&evNorm, cudaEventDisableTiming);
        cudaEventCreateWithFlags(&evCsr,  cudaEventDisableTiming);
        init_done = true;
    }

    float *pns0, *pnd0, *pns1, *pnd1;
    int *prs0, *prs1, *pe0, *pe1, *pc0, *pc1;
    int *pdo0, *pdi0, *pdo1, *pdi1;
    __nv_bfloat16 *pwHi, *pwLo, *paHi, *paLo;
    __half *pH;
    cudaGetSymbolAddress((void**)&pH,   g_bufH);
    cudaGetSymbolAddress((void**)&paHi, g_aHi);
    cudaGetSymbolAddress((void**)&paLo, g_aLo);
    cudaGetSymbolAddress((void**)&pns0, g_ns0);
    cudaGetSymbolAddress((void**)&pnd0, g_nd0);
    cudaGetSymbolAddress((void**)&pns1, g_ns1);
    cudaGetSymbolAddress((void**)&pnd1, g_nd1);
    cudaGetSymbolAddress((void**)&prs0, g_rs0);
    cudaGetSymbolAddress((void**)&prs1, g_rs1);
    cudaGetSymbolAddress((void**)&pe0,  g_eidx0);
    cudaGetSymbolAddress((void**)&pe1,  g_eidx1);
    cudaGetSymbolAddress((void**)&pc0,  g_cur0);
    cudaGetSymbolAddress((void**)&pc1,  g_cur1);
    cudaGetSymbolAddress((void**)&pdo0, g_do0);
    cudaGetSymbolAddress((void**)&pdi0, g_di0);
    cudaGetSymbolAddress((void**)&pdo1, g_do1);
    cudaGetSymbolAddress((void**)&pdi1, g_di1);
    cudaGetSymbolAddress((void**)&pwHi, g_wHi);
    cudaGetSymbolAddress((void**)&pwLo, g_wLo);

    int nb = (n + 255) / 256;
    int eb = (e + 255) / 256;
    int gb = (n + 127) / 128;
    long agg_threads = (long)n * 32;
    int ab = (int)((agg_threads + 255) / 256);
    int snb = (n + SCHUNK - 1) / SCHUNK;

    // ===== fork: graph-prep chain on s2, GEMM chain on the main stream =====
    cudaEventRecord(evRoot, 0);
    cudaStreamWaitEvent(s2, evRoot, 0);

    // --- prep chain (stream s2): degrees, norms, CSR-by-dst ---
    cudaMemsetAsync(pdo0, 0, (size_t)n * sizeof(int), s2);
    cudaMemsetAsync(pdi0, 0, (size_t)n * sizeof(int), s2);
    cudaMemsetAsync(pdo1, 0, (size_t)n * sizeof(int), s2);
    cudaMemsetAsync(pdi1, 0, (size_t)n * sizeof(int), s2);
    cudaMemsetAsync(pc0,  0, (size_t)n * sizeof(int), s2);
    cudaMemsetAsync(pc1,  0, (size_t)n * sizeof(int), s2);
    count_deg<<<eb, 256, 0, s2>>>(src0, dst0, src1, dst1, e);
    norms_k<<<nb, 256, 0, s2>>>(n);
    cudaEventRecord(evNorm, s2);          // ns0/nd0/ns1/nd1 ready
    {
        dim3 sg(snb, 2);
        scan_pass1<<<sg, 256, 0, s2>>>(pdi0, pdi1, n);
        scan_pass2<<<1, 256, 0, s2>>>(prs0, prs1, snb, n);
        scan_pass3<<<sg, 256, 0, s2>>>(pdi0, pdi1, prs0, prs1, n);
    }
    fill_csr<<<eb, 256, 0, s2>>>(src0, dst0, prs0, pc0, pe0, e);
    fill_csr<<<eb, 256, 0, s2>>>(src1, dst1, prs1, pc1, pe1, e);
    cudaEventRecord(evCsr, s2);           // CSR for both layers ready

    // --- main stream: embed GEMM (independent of prep) ---
    w_prep<<<(256 * HID + 255) / 256, 256>>>(We, 256);
    gemm_embed<<<gb, 256, GSMEM>>>(x, pwHi, pwLo, be, paHi, paLo, n);

    // --- layer 1 (GEMM needs ns0; agg needs CSR + nd0) ---
    w_prep<<<(128 * HID + 255) / 256, 256>>>(W1, 128);
    cudaStreamWaitEvent(0, evNorm, 0);
    gemm_layer<<<gb, 256, GSMEM>>>(paHi, paLo, pwHi, pwLo, pns0, pH, n);
    cudaStreamWaitEvent(0, evCsr, 0);
    agg_relu_planes<<<ab, 256>>>(pe0, prs0, pH, pnd0, b1, paHi, paLo, n);

    // --- layer 2 ---
    w_prep<<<(128 * HID + 255) / 256, 256>>>(W2, 128);
    gemm_layer<<<gb, 256, GSMEM>>>(paHi, paLo, pwHi, pwLo, pns1, pH, n);
    agg_relu_out<<<ab, 256>>>(pe1, prs1, pH, pnd1, b2, (float*)d_out, n);
}

// round 14
// speedup vs baseline: 1.3021x; 1.0623x over previous
#include <cuda_runtime.h>
#include <cuda_bf16.h>
#include <cuda_fp16.h>
#include <cstdint>

// Problem-fixed maxima (sizes also derived at runtime from in_sizes)
#define NMAX 100000
#define EMAX 1600000
#define HID  128
#define INF  256

#define SCHUNK 1024
#define SBLOCKS_MAX 128   // ceil(NMAX/SCHUNK)=98 <= 128

// ---------------- scratch (device globals: no allocation allowed) ----------
__device__ __align__(256) __half g_bufH[(size_t)NMAX * HID];   // gathered GEMM out
__device__ __align__(256) __half g_aHi[(size_t)NMAX * HID];    // A hi plane (fp16)
__device__ __align__(256) __half g_aLo[(size_t)NMAX * HID];    // A lo plane (fp16)
__device__ __align__(16)  int   g_eidx0[EMAX];
__device__ __align__(16)  int   g_eidx1[EMAX];
__device__ __align__(16)  int   g_rs0[NMAX + 1];
__device__ __align__(16)  int   g_rs1[NMAX + 1];
__device__ int g_do0[NMAX], g_di0[NMAX], g_do1[NMAX], g_di1[NMAX];
__device__ int g_cur0[NMAX], g_cur1[NMAX];
__device__ float g_ns0[NMAX], g_nd0[NMAX], g_ns1[NMAX], g_nd1[NMAX];
__device__ int g_part[2][SBLOCKS_MAX];
__device__ int g_pscan[2][SBLOCKS_MAX];
// W transposed fp16 planes (single plane each): [HID rows][K]
__device__ __align__(16) __half g_wE[HID * 256];
__device__ __align__(16) __half g_w1[HID * 128];
__device__ __align__(16) __half g_w2[HID * 128];

// ---------------- helpers ---------------------------------------------------
__device__ __forceinline__ uint32_t smem_u32(const void* p) {
    uint32_t a;
    asm("{ .reg .u64 t; cvta.to.shared.u64 t, %1; cvt.u32.u64 %0, t; }"
        : "=r"(a) : "l"(p));
    return a;
}

// split 2 floats into packed fp16x2 hi and lo (compensated)
__device__ __forceinline__ void split2h(float a, float b, uint32_t& hi, uint32_t& lo) {
    __half2 h = __floats2half2_rn(a, b);
    float la = a - __low2float(h);
    float lb = b - __high2float(h);
    __half2 l = __floats2half2_rn(la, lb);
    hi = *reinterpret_cast<uint32_t*>(&h);
    lo = *reinterpret_cast<uint32_t*>(&l);
}

#define LDSM4(r, addr) \
    asm volatile("ldmatrix.sync.aligned.m8n8.x4.shared.b16 {%0,%1,%2,%3}, [%4];" \
                 : "=r"((r)[0]), "=r"((r)[1]), "=r"((r)[2]), "=r"((r)[3]) \
                 : "r"(addr))

#define MMAF16(d, a, b0, b1) \
    asm volatile("mma.sync.aligned.m16n8k16.row.col.f32.f16.f16.f32 " \
                 "{%0,%1,%2,%3}, {%4,%5,%6,%7}, {%8,%9}, {%0,%1,%2,%3};" \
                 : "+f"((d)[0]), "+f"((d)[1]), "+f"((d)[2]), "+f"((d)[3]) \
                 : "r"((a)[0]), "r"((a)[1]), "r"((a)[2]), "r"((a)[3]), \
                   "r"(b0), "r"(b1))

// ---------------- setup kernels --------------------------------------------
__global__ void count_deg(const int* __restrict__ s0, const int* __restrict__ d0,
                          const int* __restrict__ s1, const int* __restrict__ d1, int e) {
    int i = blockIdx.x * blockDim.x + threadIdx.x;
    if (i < e) {
        atomicAdd(&g_do0[s0[i]], 1);
        atomicAdd(&g_di0[d0[i]], 1);
        atomicAdd(&g_do1[s1[i]], 1);
        atomicAdd(&g_di1[d1[i]], 1);
    }
}

__global__ void norms_k(int n) {
    int i = blockIdx.x * blockDim.x + threadIdx.x;
    if (i < n) {
        g_ns0[i] = rsqrtf(fmaxf((float)g_do0[i], 1.0f));
        g_nd0[i] = rsqrtf(fmaxf((float)g_di0[i], 1.0f));
        g_ns1[i] = rsqrtf(fmaxf((float)g_do1[i], 1.0f));
        g_nd1[i] = rsqrtf(fmaxf((float)g_di1[i], 1.0f));
    }
}

// W prep: transpose + fp16 cast.  W:[K][HID] -> out:[HID][K]
__global__ void w_prep(const float* __restrict__ W, __half* __restrict__ out, int K) {
    int idx = blockIdx.x * blockDim.x + threadIdx.x;
    if (idx < K * HID) {
        int k = idx / HID, n = idx % HID;
        out[n * K + k] = __float2half(W[idx]);
    }
}

// ---------------- grid-wide exclusive scan (3 passes, 2 arrays batched) ----
__global__ void scan_pass1(const int* __restrict__ dA, const int* __restrict__ dB, int n) {
    const int* deg = blockIdx.y ? dB : dA;
    __shared__ int sh[256];
    int base = blockIdx.x * SCHUNK + threadIdx.x * 4;
    int s = 0;
#pragma unroll
    for (int q = 0; q < 4; ++q)
        if (base + q < n) s += deg[base + q];
    sh[threadIdx.x] = s;
    __syncthreads();
#pragma unroll
    for (int off = 128; off > 0; off >>= 1) {
        if (threadIdx.x < off) sh[threadIdx.x] += sh[threadIdx.x + off];
        __syncthreads();
    }
    if (threadIdx.x == 0) g_part[blockIdx.y][blockIdx.x] = sh[0];
}

__global__ void scan_pass2(int* __restrict__ rsA, int* __restrict__ rsB,
                           int nblocks, int n) {
    __shared__ int sh[2][SBLOCKS_MAX];
    int a = threadIdx.x >> 7;
    int j = threadIdx.x & 127;
    int v = (j < nblocks) ? g_part[a][j] : 0;
    sh[a][j] = v;
    __syncthreads();
#pragma unroll
    for (int off = 1; off < SBLOCKS_MAX; off <<= 1) {
        int t = (j >= off) ? sh[a][j - off] : 0;
        __syncthreads();
        sh[a][j] += t;
        __syncthreads();
    }
    if (j < nblocks) g_pscan[a][j] = sh[a][j] - v;   // exclusive
    if (j == 127) {
        int total = sh[a][SBLOCKS_MAX - 1];
        (a ? rsB : rsA)[n] = total;
    }
}

__global__ void scan_pass3(const int* __restrict__ dA, const int* __restrict__ dB,
                           int* __restrict__ rsA, int* __restrict__ rsB, int n) {
    const int* deg = blockIdx.y ? dB : dA;
    int* rs = blockIdx.y ? rsB : rsA;
    __shared__ int sh[256];
    int base = blockIdx.x * SCHUNK + threadIdx.x * 4;
    int v[4];
    int s = 0;
#pragma unroll
    for (int q = 0; q < 4; ++q) {
        v[q] = (base + q < n) ? deg[base + q] : 0;
        s += v[q];
    }
    sh[threadIdx.x] = s;
    __syncthreads();
#pragma unroll
    for (int off = 1; off < 256; off <<= 1) {
        int t = (threadIdx.x >= off) ? sh[threadIdx.x - off] : 0;
        __syncthreads();
        sh[threadIdx.x] += t;
        __syncthreads();
    }
    int ex = sh[threadIdx.x] - s + g_pscan[blockIdx.y][blockIdx.x];
#pragma unroll
    for (int q = 0; q < 4; ++q) {
        if (base + q < n) { rs[base + q] = ex; ex += v[q]; }
    }
}

__global__ void fill_csr(const int* __restrict__ src, const int* __restrict__ dst,
                         const int* __restrict__ rs, int* __restrict__ cur,
                         int* __restrict__ eidx, int e) {
    int i = blockIdx.x * blockDim.x + threadIdx.x;
    if (i < e) {
        int d = dst[i];
        int p = atomicAdd(&cur[d], 1);
        eidx[rs[d] + p] = src[i];
    }
}

// ============== mma.sync fp16x2 GEMM (2 terms, 1 W plane) ===================
// Block: 256 threads = 8 warps (4 m x 2 n), tile 128x128, K-chunk 64 in SMEM.
// SMEM rows padded to 144 B -> conflict-free ldmatrix. 2 CTAs/SM.
#define ROWB 144
#define PLANE (128 * ROWB)
#define OFF_AHI 0
#define OFF_ALO (1 * PLANE)
#define OFF_W   (2 * PLANE)
#define GSMEM   (3 * PLANE)           // 55296 B

struct WarpCtx {
    uint32_t aHiBase, aLoBase, wBase;
    int warp_m, warp_n, lane;
};

__device__ __forceinline__ WarpCtx mk_ctx(uint32_t smb, int tid) {
    WarpCtx c;
    int wid = tid >> 5;
    c.lane = tid & 31;
    c.warp_m = wid & 3;
    c.warp_n = wid >> 2;
    const int q4 = c.lane >> 3, lr = c.lane & 7;
    const uint32_t laneA = (uint32_t)(((q4 & 1) * 8 + lr) * ROWB + (q4 >> 1) * 16);
    const uint32_t laneB = (uint32_t)(((q4 >> 1) * 8 + lr) * ROWB + (q4 & 1) * 16);
    c.aHiBase = smb + OFF_AHI + (uint32_t)(c.warp_m * 32) * ROWB + laneA;
    c.aLoBase = smb + OFF_ALO + (uint32_t)(c.warp_m * 32) * ROWB + laneA;
    c.wBase   = smb + OFF_W   + (uint32_t)(c.warp_n * 64) * ROWB + laneB;
    return c;
}

__device__ __forceinline__ void stage_w(char* sm, const __half* w, int K, int kc, int tid) {
    const int cq = (tid & 7) * 8;
    const int r0 = tid >> 3;
#pragma unroll
    for (int it = 0; it < 4; ++it) {
        int r = r0 + it * 32;
        uint4 v = *reinterpret_cast<const uint4*>(w + (size_t)r * K + kc + cq);
        *reinterpret_cast<uint4*>(sm + OFF_W + (uint32_t)(r * ROWB + cq * 2)) = v;
    }
}

__device__ __forceinline__ void compute_chunk(const WarpCtx& c, float acc[2][8][4]) {
#pragma unroll
    for (int ks = 0; ks < 4; ++ks) {
        uint32_t ah[2][4], al[2][4];
#pragma unroll
        for (int ma = 0; ma < 2; ++ma) {
            uint32_t ao = (uint32_t)(ma * 16 * ROWB + ks * 32);
            LDSM4(ah[ma], c.aHiBase + ao);
            LDSM4(al[ma], c.aLoBase + ao);
        }
#pragma unroll
        for (int nb = 0; nb < 4; ++nb) {
            uint32_t w[4];
            LDSM4(w, c.wBase + (uint32_t)(nb * 16 * ROWB + ks * 32));
#pragma unroll
            for (int ma = 0; ma < 2; ++ma) {
                MMAF16(acc[ma][nb * 2 + 0], ah[ma], w[0], w[1]);
                MMAF16(acc[ma][nb * 2 + 0], al[ma], w[0], w[1]);
                MMAF16(acc[ma][nb * 2 + 1], ah[ma], w[2], w[3]);
                MMAF16(acc[ma][nb * 2 + 1], al[ma], w[2], w[3]);
            }
        }
    }
}

// ---- EMBED GEMM: A = x fp32 [M][256] (split in staging), out = fp16 planes ----
__global__ __launch_bounds__(256, 2)
void gemm_embed(const float* __restrict__ A, const __half* __restrict__ w,
                const float* __restrict__ bias,
                __half* __restrict__ outHi, __half* __restrict__ outLo, int M) {
    constexpr int K = 256;
    extern __shared__ char sm[];
    const uint32_t smb = smem_u32(sm);
    const int tid = threadIdx.x;
    const int block_m = blockIdx.x * 128;
    WarpCtx c = mk_ctx(smb, tid);

    float acc[2][8][4];
#pragma unroll
    for (int i = 0; i < 2; ++i)
#pragma unroll
        for (int j = 0; j < 8; ++j)
#pragma unroll
            for (int q = 0; q < 4; ++q) acc[i][j][q] = 0.0f;

#pragma unroll 1
    for (int kc = 0; kc < K; kc += 64) {
        {
            const int cq = (tid & 15) * 4;
            const int r0 = tid >> 4;
#pragma unroll
            for (int it = 0; it < 8; ++it) {
                int r = r0 + it * 16;
                int gm = block_m + r;
                float4 v = make_float4(0.f, 0.f, 0.f, 0.f);
                if (gm < M)
                    v = *reinterpret_cast<const float4*>(A + (size_t)gm * K + kc + cq);
                uint32_t h0, l0, h1, l1;
                split2h(v.x, v.y, h0, l0);
                split2h(v.z, v.w, h1, l1);
                uint32_t off = (uint32_t)(r * ROWB + cq * 2);
                *reinterpret_cast<uint2*>(sm + OFF_AHI + off) = make_uint2(h0, h1);
                *reinterpret_cast<uint2*>(sm + OFF_ALO + off) = make_uint2(l0, l1);
            }
        }
        stage_w(sm, w, K, kc, tid);
        __syncthreads();
        compute_chunk(c, acc);
        __syncthreads();
    }

    const int g = c.lane >> 2, t = c.lane & 3;
#pragma unroll
    for (int ma = 0; ma < 2; ++ma) {
        int r0 = block_m + c.warp_m * 32 + ma * 16 + g;
        int r1 = r0 + 8;
#pragma unroll
        for (int na = 0; na < 8; ++na) {
            int col = c.warp_n * 64 + na * 8 + t * 2;
            float2 bv = *reinterpret_cast<const float2*>(bias + col);
            if (r0 < M) {
                uint32_t h, l;
                split2h(acc[ma][na][0] + bv.x, acc[ma][na][1] + bv.y, h, l);
                *reinterpret_cast<uint32_t*>(outHi + (size_t)r0 * HID + col) = h;
                *reinterpret_cast<uint32_t*>(outLo + (size_t)r0 * HID + col) = l;
            }
            if (r1 < M) {
                uint32_t h, l;
                split2h(acc[ma][na][2] + bv.x, acc[ma][na][3] + bv.y, h, l);
                *reinterpret_cast<uint32_t*>(outHi + (size_t)r1 * HID + col) = h;
                *reinterpret_cast<uint32_t*>(outLo + (size_t)r1 * HID + col) = l;
            }
        }
    }
}

// ---- LAYER GEMM: A = fp16 planes [M][128]; out = fp16(acc*rowscale) ----
__global__ __launch_bounds__(256, 2)
void gemm_layer(const __half* __restrict__ aHi, const __half* __restrict__ aLo,
                const __half* __restrict__ w, const float* __restrict__ rowscale,
                __half* __restrict__ C, int M) {
    constexpr int K = 128;
    extern __shared__ char sm[];
    const uint32_t smb = smem_u32(sm);
    const int tid = threadIdx.x;
    const int block_m = blockIdx.x * 128;
    WarpCtx c = mk_ctx(smb, tid);

    float acc[2][8][4];
#pragma unroll
    for (int i = 0; i < 2; ++i)
#pragma unroll
        for (int j = 0; j < 8; ++j)
#pragma unroll
            for (int q = 0; q < 4; ++q) acc[i][j][q] = 0.0f;

#pragma unroll 1
    for (int kc = 0; kc < K; kc += 64) {
        {
            const int cq = (tid & 7) * 8;
            const int r0 = tid >> 3;
#pragma unroll
            for (int it = 0; it < 4; ++it) {
                int r = r0 + it * 32;
                int gm = block_m + r;
                uint4 vh = make_uint4(0, 0, 0, 0), vl = make_uint4(0, 0, 0, 0);
                if (gm < M) {
                    vh = *reinterpret_cast<const uint4*>(aHi + (size_t)gm * K + kc + cq);
                    vl = *reinterpret_cast<const uint4*>(aLo + (size_t)gm * K + kc + cq);
                }
                uint32_t off = (uint32_t)(r * ROWB + cq * 2);
                *reinterpret_cast<uint4*>(sm + OFF_AHI + off) = vh;
                *reinterpret_cast<uint4*>(sm + OFF_ALO + off) = vl;
            }
        }
        stage_w(sm, w, K, kc, tid);
        __syncthreads();
        compute_chunk(c, acc);
        __syncthreads();
    }

    const int g = c.lane >> 2, t = c.lane & 3;
#pragma unroll
    for (int ma = 0; ma < 2; ++ma) {
        int r0 = block_m + c.warp_m * 32 + ma * 16 + g;
        int r1 = r0 + 8;
        float rs0 = (r0 < M) ? rowscale[r0] : 0.f;
        float rs1 = (r1 < M) ? rowscale[r1] : 0.f;
#pragma unroll
        for (int na = 0; na < 8; ++na) {
            int col = c.warp_n * 64 + na * 8 + t * 2;
            if (r0 < M) {
                __half2 o = __floats2half2_rn(acc[ma][na][0] * rs0, acc[ma][na][1] * rs0);
                *reinterpret_cast<__half2*>(C + (size_t)r0 * HID + col) = o;
            }
            if (r1 < M) {
                __half2 o = __floats2half2_rn(acc[ma][na][2] * rs1, acc[ma][na][3] * rs1);
                *reinterpret_cast<__half2*>(C + (size_t)r1 * HID + col) = o;
            }
        }
    }
}

// ---------------- CSR aggregation + fused epilogues ------------------------
__device__ __forceinline__ float4 agg_core(const int* __restrict__ eidx,
                                           const __half* __restrict__ B,
                                           int beg, int end, int lane) {
    float4 a0 = make_float4(0.f, 0.f, 0.f, 0.f);
    float4 a1 = make_float4(0.f, 0.f, 0.f, 0.f);
    const int co = lane * 4;
    int i = beg;
    for (; i + 3 < end; i += 4) {
        int s0 = eidx[i], s1 = eidx[i + 1], s2 = eidx[i + 2], s3 = eidx[i + 3];
        uint2 u0 = *reinterpret_cast<const uint2*>(B + (size_t)s0 * HID + co);
        uint2 u1 = *reinterpret_cast<const uint2*>(B + (size_t)s1 * HID + co);
        uint2 u2 = *reinterpret_cast<const uint2*>(B + (size_t)s2 * HID + co);
        uint2 u3 = *reinterpret_cast<const uint2*>(B + (size_t)s3 * HID + co);
        float2 f;
        f = __half22float2(*reinterpret_cast<__half2*>(&u0.x)); a0.x += f.x; a0.y += f.y;
        f = __half22float2(*reinterpret_cast<__half2*>(&u0.y)); a0.z += f.x; a0.w += f.y;
        f = __half22float2(*reinterpret_cast<__half2*>(&u1.x)); a1.x += f.x; a1.y += f.y;
        f = __half22float2(*reinterpret_cast<__half2*>(&u1.y)); a1.z += f.x; a1.w += f.y;
        f = __half22float2(*reinterpret_cast<__half2*>(&u2.x)); a0.x += f.x; a0.y += f.y;
        f = __half22float2(*reinterpret_cast<__half2*>(&u2.y)); a0.z += f.x; a0.w += f.y;
        f = __half22float2(*reinterpret_cast<__half2*>(&u3.x)); a1.x += f.x; a1.y += f.y;
        f = __half22float2(*reinterpret_cast<__half2*>(&u3.y)); a1.z += f.x; a1.w += f.y;
    }
    for (; i < end; ++i) {
        int s0 = eidx[i];
        uint2 u0 = *reinterpret_cast<const uint2*>(B + (size_t)s0 * HID + co);
        float2 f;
        f = __half22float2(*reinterpret_cast<__half2*>(&u0.x)); a0.x += f.x; a0.y += f.y;
        f = __half22float2(*reinterpret_cast<__half2*>(&u0.y)); a0.z += f.x; a0.w += f.y;
    }
    a0.x += a1.x; a0.y += a1.y; a0.z += a1.z; a0.w += a1.w;
    return a0;
}

__global__ void agg_relu_planes(const int* __restrict__ eidx, const int* __restrict__ rs,
                                const __half* __restrict__ B, const float* __restrict__ nd,
                                const float* __restrict__ bias,
                                __half* __restrict__ outHi, __half* __restrict__ outLo, int n) {
    int t = blockIdx.x * blockDim.x + threadIdx.x;
    int v = t >> 5;
    int lane = t & 31;
    if (v >= n) return;
    float4 acc = agg_core(eidx, B, rs[v], rs[v + 1], lane);
    float d = nd[v];
    float4 bv = *reinterpret_cast<const float4*>(bias + lane * 4);
    float o0 = fmaxf(fmaf(acc.x, d, bv.x), 0.f);
    float o1 = fmaxf(fmaf(acc.y, d, bv.y), 0.f);
    float o2 = fmaxf(fmaf(acc.z, d, bv.z), 0.f);
    float o3 = fmaxf(fmaf(acc.w, d, bv.w), 0.f);
    uint32_t h0, l0, h1, l1;
    split2h(o0, o1, h0, l0);
    split2h(o2, o3, h1, l1);
    size_t base = (size_t)v * HID + lane * 4;
    *reinterpret_cast<uint2*>(outHi + base) = make_uint2(h0, h1);
    *reinterpret_cast<uint2*>(outLo + base) = make_uint2(l0, l1);
}

__global__ void agg_relu_out(const int* __restrict__ eidx, const int* __restrict__ rs,
                             const __half* __restrict__ B, const float* __restrict__ nd,
                             const float* __restrict__ bias, float* __restrict__ out, int n) {
    int t = blockIdx.x * blockDim.x + threadIdx.x;
    int v = t >> 5;
    int lane = t & 31;
    if (v >= n) return;
    float4 acc = agg_core(eidx, B, rs[v], rs[v + 1], lane);
    float d = nd[v];
    float4 bv = *reinterpret_cast<const float4*>(bias + lane * 4);
    float4 o;
    o.x = fmaxf(fmaf(acc.x, d, bv.x), 0.f);
    o.y = fmaxf(fmaf(acc.y, d, bv.y), 0.f);
    o.z = fmaxf(fmaf(acc.z, d, bv.z), 0.f);
    o.w = fmaxf(fmaf(acc.w, d, bv.w), 0.f);
    *reinterpret_cast<float4*>(out + (size_t)v * HID + lane * 4) = o;
}

// ---------------- launch ----------------------------------------------------
extern "C" void kernel_launch(void* const* d_in, const int* in_sizes, int n_in,
                              void* d_out, int out_size) {
    const float* x  = (const float*)d_in[0];
    const float* We = (const float*)d_in[1];
    const float* be = (const float*)d_in[2];
    const float* W1 = (const float*)d_in[3];
    const float* b1 = (const float*)d_in[4];
    const float* W2 = (const float*)d_in[5];
    const float* b2 = (const float*)d_in[6];
    const int* src0 = (const int*)d_in[7];
    const int* dst0 = (const int*)d_in[8];
    const int* src1 = (const int*)d_in[9];
    const int* dst1 = (const int*)d_in[10];

    int n = in_sizes[0] / INF;
    int e = in_sizes[7];

    static bool init_done = false;
    static cudaStream_t s2;
    static cudaEvent_t evRoot, evNorm, evCsr;
    if (!init_done) {
        cudaFuncSetAttribute(gemm_embed, cudaFuncAttributeMaxDynamicSharedMemorySize, GSMEM);
        cudaFuncSetAttribute(gemm_layer, cudaFuncAttributeMaxDynamicSharedMemorySize, GSMEM);
        cudaStreamCreateWithFlags(&s2, cudaStreamNonBlocking);
        cudaEventCreateWithFlags(&evRoot, cudaEventDisableTiming);
        cudaEventCreateWithFlags(&evNorm, cudaEventDisableTiming);
        cudaEventCreateWithFlags(&evCsr,  cudaEventDisableTiming);
        init_done = true;
    }

    float *pns0, *pnd0, *pns1, *pnd1;
    int *prs0, *prs1, *pe0, *pe1, *pc0, *pc1;
    int *pdo0, *pdi0, *pdo1, *pdi1;
    __half *pwE, *pw1, *pw2, *paHi, *paLo, *pH;
    cudaGetSymbolAddress((void**)&pH,   g_bufH);
    cudaGetSymbolAddress((void**)&paHi, g_aHi);
    cudaGetSymbolAddress((void**)&paLo, g_aLo);
    cudaGetSymbolAddress((void**)&pns0, g_ns0);
    cudaGetSymbolAddress((void**)&pnd0, g_nd0);
    cudaGetSymbolAddress((void**)&pns1, g_ns1);
    cudaGetSymbolAddress((void**)&pnd1, g_nd1);
    cudaGetSymbolAddress((void**)&prs0, g_rs0);
    cudaGetSymbolAddress((void**)&prs1, g_rs1);
    cudaGetSymbolAddress((void**)&pe0,  g_eidx0);
    cudaGetSymbolAddress((void**)&pe1,  g_eidx1);
    cudaGetSymbolAddress((void**)&pc0,  g_cur0);
    cudaGetSymbolAddress((void**)&pc1,  g_cur1);
    cudaGetSymbolAddress((void**)&pdo0, g_do0);
    cudaGetSymbolAddress((void**)&pdi0, g_di0);
    cudaGetSymbolAddress((void**)&pdo1, g_do1);
    cudaGetSymbolAddress((void**)&pdi1, g_di1);
    cudaGetSymbolAddress((void**)&pwE,  g_wE);
    cudaGetSymbolAddress((void**)&pw1,  g_w1);
    cudaGetSymbolAddress((void**)&pw2,  g_w2);

    int nb = (n + 255) / 256;
    int eb = (e + 255) / 256;
    int gb = (n + 127) / 128;
    long agg_threads = (long)n * 32;
    int ab = (int)((agg_threads + 255) / 256);
    int snb = (n + SCHUNK - 1) / SCHUNK;

    // ===== fork: prep chain on s2, GEMM chain on the main stream =====
    cudaEventRecord(evRoot, 0);
    cudaStreamWaitEvent(s2, evRoot, 0);

    // --- prep chain (stream s2): W1/W2 prep, degrees, norms, CSR-by-dst ---
    cudaMemsetAsync(pdo0, 0, (size_t)n * sizeof(int), s2);
    cudaMemsetAsync(pdi0, 0, (size_t)n * sizeof(int), s2);
    cudaMemsetAsync(pdo1, 0, (size_t)n * sizeof(int), s2);
    cudaMemsetAsync(pdi1, 0, (size_t)n * sizeof(int), s2);
    cudaMemsetAsync(pc0,  0, (size_t)n * sizeof(int), s2);
    cudaMemsetAsync(pc1,  0, (size_t)n * sizeof(int), s2);
    w_prep<<<(128 * HID + 255) / 256, 256, 0, s2>>>(W1, pw1, 128);
    w_prep<<<(128 * HID + 255) / 256, 256, 0, s2>>>(W2, pw2, 128);
    count_deg<<<eb, 256, 0, s2>>>(src0, dst0, src1, dst1, e);
    norms_k<<<nb, 256, 0, s2>>>(n);
    cudaEventRecord(evNorm, s2);          // ns/nd + W1/W2 planes ready
    {
        dim3 sg(snb, 2);
        scan_pass1<<<sg, 256, 0, s2>>>(pdi0, pdi1, n);
        scan_pass2<<<1, 256, 0, s2>>>(prs0, prs1, snb, n);
        scan_pass3<<<sg, 256, 0, s2>>>(pdi0, pdi1, prs0, prs1, n);
    }
    fill_csr<<<eb, 256, 0, s2>>>(src0, dst0, prs0, pc0, pe0, e);
    fill_csr<<<eb, 256, 0, s2>>>(src1, dst1, prs1, pc1, pe1, e);
    cudaEventRecord(evCsr, s2);           // CSR for both layers ready

    // --- main stream: embed GEMM (independent of prep) ---
    w_prep<<<(256 * HID + 255) / 256, 256>>>(We, pwE, 256);
    gemm_embed<<<gb, 256, GSMEM>>>(x, pwE, be, paHi, paLo, n);

    // --- layer 1 (GEMM needs ns0 + W1 plane; agg needs CSR + nd0) ---
    cudaStreamWaitEvent(0, evNorm, 0);
    gemm_layer<<<gb, 256, GSMEM>>>(paHi, paLo, pw1, pns0, pH, n);
    cudaStreamWaitEvent(0, evCsr, 0);
    agg_relu_planes<<<ab, 256>>>(pe0, prs0, pH, pnd0, b1, paHi, paLo, n);

    // --- layer 2 ---
    gemm_layer<<<gb, 256, GSMEM>>>(paHi, paLo, pw2, pns1, pH, n);
    agg_relu_out<<<ab, 256>>>(pe1, prs1, pH, pnd1, b2, (float*)d_out, n);
}

// round 16
// speedup vs baseline: 1.4897x; 1.1441x over previous
#include <cuda_runtime.h>
#include <cuda_fp16.h>
#include <cstdint>

// Problem-fixed maxima (sizes also derived at runtime from in_sizes)
#define NMAX 100000
#define EMAX 1600000
#define HID  128
#define INF  256

#define SCHUNK 1024
#define SBLOCKS_MAX 128   // ceil(NMAX/SCHUNK)=98 <= 128

// ---------------- scratch (device globals: no allocation allowed) ----------
__device__ __align__(256) __half g_bufH[(size_t)NMAX * HID];   // gathered GEMM out
__device__ __align__(256) __half g_aH[(size_t)NMAX * HID];     // A plane (fp16)
__device__ __align__(16)  int   g_eidx0[EMAX];
__device__ __align__(16)  int   g_eidx1[EMAX];
__device__ __align__(16)  int   g_rs0[NMAX + 1];
__device__ __align__(16)  int   g_rs1[NMAX + 1];
__device__ int g_do0[NMAX], g_di0[NMAX], g_do1[NMAX], g_di1[NMAX];
__device__ int g_cur0[NMAX], g_cur1[NMAX];
__device__ float g_ns0[NMAX], g_nd0[NMAX], g_ns1[NMAX], g_nd1[NMAX];
__device__ int g_part[2][SBLOCKS_MAX];
__device__ int g_pscan[2][SBLOCKS_MAX];
// W transposed fp16 planes: [HID rows][K]
__device__ __align__(16) __half g_wE[HID * 256];
__device__ __align__(16) __half g_w1[HID * 128];
__device__ __align__(16) __half g_w2[HID * 128];

// ---------------- helpers ---------------------------------------------------
__device__ __forceinline__ uint32_t smem_u32(const void* p) {
    uint32_t a;
    asm("{ .reg .u64 t; cvta.to.shared.u64 t, %1; cvt.u32.u64 %0, t; }"
        : "=r"(a) : "l"(p));
    return a;
}

__device__ __forceinline__ uint32_t h2u(__half2 h) {
    return *reinterpret_cast<uint32_t*>(&h);
}

#define LDSM4(r, addr) \
    asm volatile("ldmatrix.sync.aligned.m8n8.x4.shared.b16 {%0,%1,%2,%3}, [%4];" \
                 : "=r"((r)[0]), "=r"((r)[1]), "=r"((r)[2]), "=r"((r)[3]) \
                 : "r"(addr))

#define MMAF16(d, a, b0, b1) \
    asm volatile("mma.sync.aligned.m16n8k16.row.col.f32.f16.f16.f32 " \
                 "{%0,%1,%2,%3}, {%4,%5,%6,%7}, {%8,%9}, {%0,%1,%2,%3};" \
                 : "+f"((d)[0]), "+f"((d)[1]), "+f"((d)[2]), "+f"((d)[3]) \
                 : "r"((a)[0]), "r"((a)[1]), "r"((a)[2]), "r"((a)[3]), \
                   "r"(b0), "r"(b1))

// ---------------- setup kernels --------------------------------------------
__global__ void count_deg(const int* __restrict__ s0, const int* __restrict__ d0,
                          const int* __restrict__ s1, const int* __restrict__ d1, int e) {
    int i = blockIdx.x * blockDim.x + threadIdx.x;
    if (i < e) {
        atomicAdd(&g_do0[s0[i]], 1);
        atomicAdd(&g_di0[d0[i]], 1);
        atomicAdd(&g_do1[s1[i]], 1);
        atomicAdd(&g_di1[d1[i]], 1);
    }
}

__global__ void norms_k(int n) {
    int i = blockIdx.x * blockDim.x + threadIdx.x;
    if (i < n) {
        g_ns0[i] = rsqrtf(fmaxf((float)g_do0[i], 1.0f));
        g_nd0[i] = rsqrtf(fmaxf((float)g_di0[i], 1.0f));
        g_ns1[i] = rsqrtf(fmaxf((float)g_do1[i], 1.0f));
        g_nd1[i] = rsqrtf(fmaxf((float)g_di1[i], 1.0f));
    }
}

// W prep: transpose + fp16 cast.  W:[K][HID] -> out:[HID][K]
__global__ void w_prep(const float* __restrict__ W, __half* __restrict__ out, int K) {
    int idx = blockIdx.x * blockDim.x + threadIdx.x;
    if (idx < K * HID) {
        int k = idx / HID, n = idx % HID;
        out[n * K + k] = __float2half(W[idx]);
    }
}

// ---------------- grid-wide exclusive scan (3 passes, 2 arrays batched) ----
__global__ void scan_pass1(const int* __restrict__ dA, const int* __restrict__ dB, int n) {
    const int* deg = blockIdx.y ? dB : dA;
    __shared__ int sh[256];
    int base = blockIdx.x * SCHUNK + threadIdx.x * 4;
    int s = 0;
#pragma unroll
    for (int q = 0; q < 4; ++q)
        if (base + q < n) s += deg[base + q];
    sh[threadIdx.x] = s;
    __syncthreads();
#pragma unroll
    for (int off = 128; off > 0; off >>= 1) {
        if (threadIdx.x < off) sh[threadIdx.x] += sh[threadIdx.x + off];
        __syncthreads();
    }
    if (threadIdx.x == 0) g_part[blockIdx.y][blockIdx.x] = sh[0];
}

__global__ void scan_pass2(int* __restrict__ rsA, int* __restrict__ rsB,
                           int nblocks, int n) {
    __shared__ int sh[2][SBLOCKS_MAX];
    int a = threadIdx.x >> 7;
    int j = threadIdx.x & 127;
    int v = (j < nblocks) ? g_part[a][j] : 0;
    sh[a][j] = v;
    __syncthreads();
#pragma unroll
    for (int off = 1; off < SBLOCKS_MAX; off <<= 1) {
        int t = (j >= off) ? sh[a][j - off] : 0;
        __syncthreads();
        sh[a][j] += t;
        __syncthreads();
    }
    if (j < nblocks) g_pscan[a][j] = sh[a][j] - v;   // exclusive
    if (j == 127) {
        int total = sh[a][SBLOCKS_MAX - 1];
        (a ? rsB : rsA)[n] = total;
    }
}

__global__ void scan_pass3(const int* __restrict__ dA, const int* __restrict__ dB,
                           int* __restrict__ rsA, int* __restrict__ rsB, int n) {
    const int* deg = blockIdx.y ? dB : dA;
    int* rs = blockIdx.y ? rsB : rsA;
    __shared__ int sh[256];
    int base = blockIdx.x * SCHUNK + threadIdx.x * 4;
    int v[4];
    int s = 0;
#pragma unroll
    for (int q = 0; q < 4; ++q) {
        v[q] = (base + q < n) ? deg[base + q] : 0;
        s += v[q];
    }
    sh[threadIdx.x] = s;
    __syncthreads();
#pragma unroll
    for (int off = 1; off < 256; off <<= 1) {
        int t = (threadIdx.x >= off) ? sh[threadIdx.x - off] : 0;
        __syncthreads();
        sh[threadIdx.x] += t;
        __syncthreads();
    }
    int ex = sh[threadIdx.x] - s + g_pscan[blockIdx.y][blockIdx.x];
#pragma unroll
    for (int q = 0; q < 4; ++q) {
        if (base + q < n) { rs[base + q] = ex; ex += v[q]; }
    }
}

__global__ void fill_csr(const int* __restrict__ src, const int* __restrict__ dst,
                         const int* __restrict__ rs, int* __restrict__ cur,
                         int* __restrict__ eidx, int e) {
    int i = blockIdx.x * blockDim.x + threadIdx.x;
    if (i < e) {
        int d = dst[i];
        int p = atomicAdd(&cur[d], 1);
        eidx[rs[d] + p] = src[i];
    }
}

// ============== mma.sync fp16 GEMM (1 A plane, 1 W plane) ===================
// Block: 256 threads = 8 warps (4 m x 2 n), tile 128x128, K-chunk 64 in SMEM.
// SMEM rows padded to 144 B -> conflict-free ldmatrix. 2 CTAs/SM.
#define ROWB 144
#define PLANE (128 * ROWB)
#define OFF_A 0
#define OFF_W (1 * PLANE)
#define GSMEM (2 * PLANE)             // 36864 B

struct WarpCtx {
    uint32_t aBase, wBase;
    int warp_m, warp_n, lane;
};

__device__ __forceinline__ WarpCtx mk_ctx(uint32_t smb, int tid) {
    WarpCtx c;
    int wid = tid >> 5;
    c.lane = tid & 31;
    c.warp_m = wid & 3;
    c.warp_n = wid >> 2;
    const int q4 = c.lane >> 3, lr = c.lane & 7;
    const uint32_t laneA = (uint32_t)(((q4 & 1) * 8 + lr) * ROWB + (q4 >> 1) * 16);
    const uint32_t laneB = (uint32_t)(((q4 >> 1) * 8 + lr) * ROWB + (q4 & 1) * 16);
    c.aBase = smb + OFF_A + (uint32_t)(c.warp_m * 32) * ROWB + laneA;
    c.wBase = smb + OFF_W + (uint32_t)(c.warp_n * 64) * ROWB + laneB;
    return c;
}

__device__ __forceinline__ void stage_w(char* sm, const __half* w, int K, int kc, int tid) {
    const int cq = (tid & 7) * 8;
    const int r0 = tid >> 3;
#pragma unroll
    for (int it = 0; it < 4; ++it) {
        int r = r0 + it * 32;
        uint4 v = *reinterpret_cast<const uint4*>(w + (size_t)r * K + kc + cq);
        *reinterpret_cast<uint4*>(sm + OFF_W + (uint32_t)(r * ROWB + cq * 2)) = v;
    }
}

__device__ __forceinline__ void compute_chunk(const WarpCtx& c, float acc[2][8][4]) {
#pragma unroll
    for (int ks = 0; ks < 4; ++ks) {
        uint32_t a[2][4];
#pragma unroll
        for (int ma = 0; ma < 2; ++ma)
            LDSM4(a[ma], c.aBase + (uint32_t)(ma * 16 * ROWB + ks * 32));
#pragma unroll
        for (int nb = 0; nb < 4; ++nb) {
            uint32_t w[4];
            LDSM4(w, c.wBase + (uint32_t)(nb * 16 * ROWB + ks * 32));
#pragma unroll
            for (int ma = 0; ma < 2; ++ma) {
                MMAF16(acc[ma][nb * 2 + 0], a[ma], w[0], w[1]);
                MMAF16(acc[ma][nb * 2 + 1], a[ma], w[2], w[3]);
            }
        }
    }
}

// ---- EMBED GEMM: A = x fp32 [M][256] (fp16 cast in staging), out = fp16 ----
__global__ __launch_bounds__(256, 2)
void gemm_embed(const float* __restrict__ A, const __half* __restrict__ w,
                const float* __restrict__ bias, __half* __restrict__ outH, int M) {
    constexpr int K = 256;
    extern __shared__ char sm[];
    const uint32_t smb = smem_u32(sm);
    const int tid = threadIdx.x;
    const int block_m = blockIdx.x * 128;
    WarpCtx c = mk_ctx(smb, tid);

    float acc[2][8][4];
#pragma unroll
    for (int i = 0; i < 2; ++i)
#pragma unroll
        for (int j = 0; j < 8; ++j)
#pragma unroll
            for (int q = 0; q < 4; ++q) acc[i][j][q] = 0.0f;

#pragma unroll 1
    for (int kc = 0; kc < K; kc += 64) {
        {
            const int cq = (tid & 15) * 4;
            const int r0 = tid >> 4;
#pragma unroll
            for (int it = 0; it < 8; ++it) {
                int r = r0 + it * 16;
                int gm = block_m + r;
                float4 v = make_float4(0.f, 0.f, 0.f, 0.f);
                if (gm < M)
                    v = *reinterpret_cast<const float4*>(A + (size_t)gm * K + kc + cq);
                uint2 h = make_uint2(h2u(__floats2half2_rn(v.x, v.y)),
                                     h2u(__floats2half2_rn(v.z, v.w)));
                *reinterpret_cast<uint2*>(sm + OFF_A + (uint32_t)(r * ROWB + cq * 2)) = h;
            }
        }
        stage_w(sm, w, K, kc, tid);
        __syncthreads();
        compute_chunk(c, acc);
        __syncthreads();
    }

    const int g = c.lane >> 2, t = c.lane & 3;
#pragma unroll
    for (int ma = 0; ma < 2; ++ma) {
        int r0 = block_m + c.warp_m * 32 + ma * 16 + g;
        int r1 = r0 + 8;
#pragma unroll
        for (int na = 0; na < 8; ++na) {
            int col = c.warp_n * 64 + na * 8 + t * 2;
            float2 bv = *reinterpret_cast<const float2*>(bias + col);
            if (r0 < M) {
                __half2 o = __floats2half2_rn(acc[ma][na][0] + bv.x, acc[ma][na][1] + bv.y);
                *reinterpret_cast<__half2*>(outH + (size_t)r0 * HID + col) = o;
            }
            if (r1 < M) {
                __half2 o = __floats2half2_rn(acc[ma][na][2] + bv.x, acc[ma][na][3] + bv.y);
                *reinterpret_cast<__half2*>(outH + (size_t)r1 * HID + col) = o;
            }
        }
    }
}

// ---- LAYER GEMM: A = fp16 plane [M][128]; out = fp16(acc*rowscale) ----
__global__ __launch_bounds__(256, 2)
void gemm_layer(const __half* __restrict__ aH, const __half* __restrict__ w,
                const float* __restrict__ rowscale, __half* __restrict__ C, int M) {
    constexpr int K = 128;
    extern __shared__ char sm[];
    const uint32_t smb = smem_u32(sm);
    const int tid = threadIdx.x;
    const int block_m = blockIdx.x * 128;
    WarpCtx c = mk_ctx(smb, tid);

    float acc[2][8][4];
#pragma unroll
    for (int i = 0; i < 2; ++i)
#pragma unroll
        for (int j = 0; j < 8; ++j)
#pragma unroll
            for (int q = 0; q < 4; ++q) acc[i][j][q] = 0.0f;

#pragma unroll 1
    for (int kc = 0; kc < K; kc += 64) {
        {
            const int cq = (tid & 7) * 8;
            const int r0 = tid >> 3;
#pragma unroll
            for (int it = 0; it < 4; ++it) {
                int r = r0 + it * 32;
                int gm = block_m + r;
                uint4 v = make_uint4(0, 0, 0, 0);
                if (gm < M)
                    v = *reinterpret_cast<const uint4*>(aH + (size_t)gm * K + kc + cq);
                *reinterpret_cast<uint4*>(sm + OFF_A + (uint32_t)(r * ROWB + cq * 2)) = v;
            }
        }
        stage_w(sm, w, K, kc, tid);
        __syncthreads();
        compute_chunk(c, acc);
        __syncthreads();
    }

    const int g = c.lane >> 2, t = c.lane & 3;
#pragma unroll
    for (int ma = 0; ma < 2; ++ma) {
        int r0 = block_m + c.warp_m * 32 + ma * 16 + g;
        int r1 = r0 + 8;
        float rs0 = (r0 < M) ? rowscale[r0] : 0.f;
        float rs1 = (r1 < M) ? rowscale[r1] : 0.f;
#pragma unroll
        for (int na = 0; na < 8; ++na) {
            int col = c.warp_n * 64 + na * 8 + t * 2;
            if (r0 < M) {
                __half2 o = __floats2half2_rn(acc[ma][na][0] * rs0, acc[ma][na][1] * rs0);
                *reinterpret_cast<__half2*>(C + (size_t)r0 * HID + col) = o;
            }
            if (r1 < M) {
                __half2 o = __floats2half2_rn(acc[ma][na][2] * rs1, acc[ma][na][3] * rs1);
                *reinterpret_cast<__half2*>(C + (size_t)r1 * HID + col) = o;
            }
        }
    }
}

// ---------------- CSR aggregation + fused epilogues ------------------------
__device__ __forceinline__ float4 agg_core(const int* __restrict__ eidx,
                                           const __half* __restrict__ B,
                                           int beg, int end, int lane) {
    float4 a0 = make_float4(0.f, 0.f, 0.f, 0.f);
    float4 a1 = make_float4(0.f, 0.f, 0.f, 0.f);
    const int co = lane * 4;
    int i = beg;
    for (; i + 3 < end; i += 4) {
        int s0 = eidx[i], s1 = eidx[i + 1], s2 = eidx[i + 2], s3 = eidx[i + 3];
        uint2 u0 = *reinterpret_cast<const uint2*>(B + (size_t)s0 * HID + co);
        uint2 u1 = *reinterpret_cast<const uint2*>(B + (size_t)s1 * HID + co);
        uint2 u2 = *reinterpret_cast<const uint2*>(B + (size_t)s2 * HID + co);
        uint2 u3 = *reinterpret_cast<const uint2*>(B + (size_t)s3 * HID + co);
        float2 f;
        f = __half22float2(*reinterpret_cast<__half2*>(&u0.x)); a0.x += f.x; a0.y += f.y;
        f = __half22float2(*reinterpret_cast<__half2*>(&u0.y)); a0.z += f.x; a0.w += f.y;
        f = __half22float2(*reinterpret_cast<__half2*>(&u1.x)); a1.x += f.x; a1.y += f.y;
        f = __half22float2(*reinterpret_cast<__half2*>(&u1.y)); a1.z += f.x; a1.w += f.y;
        f = __half22float2(*reinterpret_cast<__half2*>(&u2.x)); a0.x += f.x; a0.y += f.y;
        f = __half22float2(*reinterpret_cast<__half2*>(&u2.y)); a0.z += f.x; a0.w += f.y;
        f = __half22float2(*reinterpret_cast<__half2*>(&u3.x)); a1.x += f.x; a1.y += f.y;
        f = __half22float2(*reinterpret_cast<__half2*>(&u3.y)); a1.z += f.x; a1.w += f.y;
    }
    for (; i < end; ++i) {
        int s0 = eidx[i];
        uint2 u0 = *reinterpret_cast<const uint2*>(B + (size_t)s0 * HID + co);
        float2 f;
        f = __half22float2(*reinterpret_cast<__half2*>(&u0.x)); a0.x += f.x; a0.y += f.y;
        f = __half22float2(*reinterpret_cast<__half2*>(&u0.y)); a0.z += f.x; a0.w += f.y;
    }
    a0.x += a1.x; a0.y += a1.y; a0.z += a1.z; a0.w += a1.w;
    return a0;
}

// layer-1 agg: out = fp16(relu(acc*nd + bias)) -> next GEMM's A plane
__global__ void agg_relu_plane(const int* __restrict__ eidx, const int* __restrict__ rs,
                               const __half* __restrict__ B, const float* __restrict__ nd,
                               const float* __restrict__ bias,
                               __half* __restrict__ outH, int n) {
    int t = blockIdx.x * blockDim.x + threadIdx.x;
    int v = t >> 5;
    int lane = t & 31;
    if (v >= n) return;
    float4 acc = agg_core(eidx, B, rs[v], rs[v + 1], lane);
    float d = nd[v];
    float4 bv = *reinterpret_cast<const float4*>(bias + lane * 4);
    float o0 = fmaxf(fmaf(acc.x, d, bv.x), 0.f);
    float o1 = fmaxf(fmaf(acc.y, d, bv.y), 0.f);
    float o2 = fmaxf(fmaf(acc.z, d, bv.z), 0.f);
    float o3 = fmaxf(fmaf(acc.w, d, bv.w), 0.f);
    uint2 h = make_uint2(h2u(__floats2half2_rn(o0, o1)), h2u(__floats2half2_rn(o2, o3)));
    *reinterpret_cast<uint2*>(outH + (size_t)v * HID + lane * 4) = h;
}

// layer-2 agg: out = relu(acc*nd + bias) -> fp32 (final output)
__global__ void agg_relu_out(const int* __restrict__ eidx, const int* __restrict__ rs,
                             const __half* __restrict__ B, const float* __restrict__ nd,
                             const float* __restrict__ bias, float* __restrict__ out, int n) {
    int t = blockIdx.x * blockDim.x + threadIdx.x;
    int v = t >> 5;
    int lane = t & 31;
    if (v >= n) return;
    float4 acc = agg_core(eidx, B, rs[v], rs[v + 1], lane);
    float d = nd[v];
    float4 bv = *reinterpret_cast<const float4*>(bias + lane * 4);
    float4 o;
    o.x = fmaxf(fmaf(acc.x, d, bv.x), 0.f);
    o.y = fmaxf(fmaf(acc.y, d, bv.y), 0.f);
    o.z = fmaxf(fmaf(acc.z, d, bv.z), 0.f);
    o.w = fmaxf(fmaf(acc.w, d, bv.w), 0.f);
    *reinterpret_cast<float4*>(out + (size_t)v * HID + lane * 4) = o;
}

// ---------------- launch ----------------------------------------------------
extern "C" void kernel_launch(void* const* d_in, const int* in_sizes, int n_in,
                              void* d_out, int out_size) {
    const float* x  = (const float*)d_in[0];
    const float* We = (const float*)d_in[1];
    const float* be = (const float*)d_in[2];
    const float* W1 = (const float*)d_in[3];
    const float* b1 = (const float*)d_in[4];
    const float* W2 = (const float*)d_in[5];
    const float* b2 = (const float*)d_in[6];
    const int* src0 = (const int*)d_in[7];
    const int* dst0 = (const int*)d_in[8];
    const int* src1 = (const int*)d_in[9];
    const int* dst1 = (const int*)d_in[10];

    int n = in_sizes[0] / INF;
    int e = in_sizes[7];

    static bool init_done = false;
    static cudaStream_t s2;
    static cudaEvent_t evRoot, evNorm, evCsr;
    if (!init_done) {
        cudaFuncSetAttribute(gemm_embed, cudaFuncAttributeMaxDynamicSharedMemorySize, GSMEM);
        cudaFuncSetAttribute(gemm_layer, cudaFuncAttributeMaxDynamicSharedMemorySize, GSMEM);
        cudaStreamCreateWithFlags(&s2, cudaStreamNonBlocking);
        cudaEventCreateWithFlags(&evRoot, cudaEventDisableTiming);
        cudaEventCreateWithFlags(&evNorm, cudaEventDisableTiming);
        cudaEventCreateWithFlags(&evCsr,  cudaEventDisableTiming);
        init_done = true;
    }

    float *pns0, *pnd0, *pns1, *pnd1;
    int *prs0, *prs1, *pe0, *pe1, *pc0, *pc1;
    int *pdo0, *pdi0, *pdo1, *pdi1;
    __half *pwE, *pw1, *pw2, *paH, *pH;
    cudaGetSymbolAddress((void**)&pH,   g_bufH);
    cudaGetSymbolAddress((void**)&paH,  g_aH);
    cudaGetSymbolAddress((void**)&pns0, g_ns0);
    cudaGetSymbolAddress((void**)&pnd0, g_nd0);
    cudaGetSymbolAddress((void**)&pns1, g_ns1);
    cudaGetSymbolAddress((void**)&pnd1, g_nd1);
    cudaGetSymbolAddress((void**)&prs0, g_rs0);
    cudaGetSymbolAddress((void**)&prs1, g_rs1);
    cudaGetSymbolAddress((void**)&pe0,  g_eidx0);
    cudaGetSymbolAddress((void**)&pe1,  g_eidx1);
    cudaGetSymbolAddress((void**)&pc0,  g_cur0);
    cudaGetSymbolAddress((void**)&pc1,  g_cur1);
    cudaGetSymbolAddress((void**)&pdo0, g_do0);
    cudaGetSymbolAddress((void**)&pdi0, g_di0);
    cudaGetSymbolAddress((void**)&pdo1, g_do1);
    cudaGetSymbolAddress((void**)&pdi1, g_di1);
    cudaGetSymbolAddress((void**)&pwE,  g_wE);
    cudaGetSymbolAddress((void**)&pw1,  g_w1);
    cudaGetSymbolAddress((void**)&pw2,  g_w2);

    int nb = (n + 255) / 256;
    int eb = (e + 255) / 256;
    int gb = (n + 127) / 128;
    long agg_threads = (long)n * 32;
    int ab = (int)((agg_threads + 255) / 256);
    int snb = (n + SCHUNK - 1) / SCHUNK;

    // ===== fork: prep chain on s2, GEMM chain on the main stream =====
    cudaEventRecord(evRoot, 0);
    cudaStreamWaitEvent(s2, evRoot, 0);

    // --- prep chain (stream s2): W1/W2 prep, degrees, norms, CSR-by-dst ---
    cudaMemsetAsync(pdo0, 0, (size_t)n * sizeof(int), s2);
    cudaMemsetAsync(pdi0, 0, (size_t)n * sizeof(int), s2);
    cudaMemsetAsync(pdo1, 0, (size_t)n * sizeof(int), s2);
    cudaMemsetAsync(pdi1, 0, (size_t)n * sizeof(int), s2);
    cudaMemsetAsync(pc0,  0, (size_t)n * sizeof(int), s2);
    cudaMemsetAsync(pc1,  0, (size_t)n * sizeof(int), s2);
    w_prep<<<(128 * HID + 255) / 256, 256, 0, s2>>>(W1, pw1, 128);
    w_prep<<<(128 * HID + 255) / 256, 256, 0, s2>>>(W2, pw2, 128);
    count_deg<<<eb, 256, 0, s2>>>(src0, dst0, src1, dst1, e);
    norms_k<<<nb, 256, 0, s2>>>(n);
    cudaEventRecord(evNorm, s2);          // ns/nd + W1/W2 planes ready
    {
        dim3 sg(snb, 2);
        scan_pass1<<<sg, 256, 0, s2>>>(pdi0, pdi1, n);
        scan_pass2<<<1, 256, 0, s2>>>(prs0, prs1, snb, n);
        scan_pass3<<<sg, 256, 0, s2>>>(pdi0, pdi1, prs0, prs1, n);
    }
    fill_csr<<<eb, 256, 0, s2>>>(src0, dst0, prs0, pc0, pe0, e);
    fill_csr<<<eb, 256, 0, s2>>>(src1, dst1, prs1, pc1, pe1, e);
    cudaEventRecord(evCsr, s2);           // CSR for both layers ready

    // --- main stream: embed GEMM (independent of prep) ---
    w_prep<<<(256 * HID + 255) / 256, 256>>>(We, pwE, 256);
    gemm_embed<<<gb, 256, GSMEM>>>(x, pwE, be, paH, n);

    // --- layer 1 (GEMM needs ns0 + W1 plane; agg needs CSR + nd0) ---
    cudaStreamWaitEvent(0, evNorm, 0);
    gemm_layer<<<gb, 256, GSMEM>>>(paH, pw1, pns0, pH, n);
    cudaStreamWaitEvent(0, evCsr, 0);
    agg_relu_plane<<<ab, 256>>>(pe0, prs0, pH, pnd0, b1, paH, n);

    // --- layer 2 ---
    gemm_layer<<<gb, 256, GSMEM>>>(paH, pw2, pns1, pH, n);
    agg_relu_out<<<ab, 256>>>(pe1, prs1, pH, pnd1, b2, (float*)d_out, n);
}